// round 1
// baseline (speedup 1.0000x reference)
#include <cuda_runtime.h>
#include <cstddef>

// ---------------- problem constants ----------------
constexpr int Bn  = 6;
constexpr int Nn  = 4096;
constexpr int QD  = 320;
constexpr int CN  = 77;
constexpr int CD  = 768;
constexpr int Hh  = 8;
constexpr int DH  = 40;
constexpr int ID  = Hh * DH;          // 320 inner dim
constexpr float SCALE = 0.15811388300841897f; // 40^-0.5

constexpr int MROWS = Bn * Nn;        // 24576
constexpr int KVROWS = Bn * CN;       // 462

// ---------------- scratch (static device memory; no allocs allowed) ------
__device__ float g_q [ (size_t)MROWS * ID ];     // q projection, (B*N, 320)
__device__ float g_o [ (size_t)MROWS * ID ];     // attn@v merged heads, (B*N, 320)
__device__ float g_kv[ (size_t)KVROWS * 2 * ID ];// (B*CN, 640): cols [0,320)=K, [320,640)=V

// =====================================================================
// Big SGEMM: C(MxN) = A(MxK) @ B(KxN) (+bias). M % 128 == 0, N % 64 == 0,
// K % 16 == 0 (all true for our 24576x320x320 uses). Row-major everywhere.
// 128x64 tile, BK=16, 256 threads, 8x4 microtile.
// =====================================================================
template<bool BIAS>
__global__ void __launch_bounds__(256) sgemm_big(
    const float* __restrict__ A, const float* __restrict__ Bm,
    const float* __restrict__ bias, float* __restrict__ C,
    int M, int N, int K)
{
    constexpr int BM = 128, BN = 64, BK = 16;
    __shared__ float As[BK][BM + 4];
    __shared__ float Bs[BK][BN];

    const int tid = threadIdx.x;
    const int tx  = tid & 15;           // 0..15 -> column group (4 cols)
    const int ty  = tid >> 4;           // 0..15 -> row group (8 rows)
    const int rowBase = blockIdx.y * BM;
    const int colBase = blockIdx.x * BN;

    // A tile load map: 512 float4 loads -> thread covers l = tid and tid+256
    const int ar = tid >> 2;            // 0..63
    const int ac = (tid & 3) << 2;      // 0,4,8,12
    // B tile load map: 256 float4 loads
    const int br = tid >> 4;            // 0..15
    const int bc = (tid & 15) << 2;     // 0..60

    float acc[8][4];
    #pragma unroll
    for (int i = 0; i < 8; i++)
        #pragma unroll
        for (int j = 0; j < 4; j++) acc[i][j] = 0.f;

    for (int k0 = 0; k0 < K; k0 += BK) {
        float4 a0 = *(const float4*)&A[(size_t)(rowBase + ar     ) * K + k0 + ac];
        float4 a1 = *(const float4*)&A[(size_t)(rowBase + ar + 64) * K + k0 + ac];
        float4 b0 = *(const float4*)&Bm[(size_t)(k0 + br) * N + colBase + bc];

        As[ac+0][ar] = a0.x; As[ac+1][ar] = a0.y; As[ac+2][ar] = a0.z; As[ac+3][ar] = a0.w;
        As[ac+0][ar+64] = a1.x; As[ac+1][ar+64] = a1.y; As[ac+2][ar+64] = a1.z; As[ac+3][ar+64] = a1.w;
        *(float4*)&Bs[br][bc] = b0;
        __syncthreads();

        #pragma unroll
        for (int kk = 0; kk < BK; kk++) {
            float a[8], b[4];
            #pragma unroll
            for (int i = 0; i < 8; i++) a[i] = As[kk][ty * 8 + i];
            #pragma unroll
            for (int j = 0; j < 4; j++) b[j] = Bs[kk][tx * 4 + j];
            #pragma unroll
            for (int i = 0; i < 8; i++)
                #pragma unroll
                for (int j = 0; j < 4; j++) acc[i][j] += a[i] * b[j];
        }
        __syncthreads();
    }

    const int c = colBase + tx * 4;
    float b0 = 0.f, b1 = 0.f, b2 = 0.f, b3 = 0.f;
    if (BIAS) { b0 = bias[c+0]; b1 = bias[c+1]; b2 = bias[c+2]; b3 = bias[c+3]; }
    #pragma unroll
    for (int i = 0; i < 8; i++) {
        const int r = rowBase + ty * 8 + i;
        float4 v;
        v.x = acc[i][0] + b0; v.y = acc[i][1] + b1;
        v.z = acc[i][2] + b2; v.w = acc[i][3] + b3;
        *(float4*)&C[(size_t)r * N + c] = v;
    }
}

// =====================================================================
// K/V projection in ONE launch: C(462x640) where cols [0,320)=ctx@Wk,
// [320,640)=ctx@Wv. 64x64 tile, BK=16, 256 threads, 4x4 microtile.
// Row bounds guarded (462 not a tile multiple).
// =====================================================================
__global__ void __launch_bounds__(256) sgemm_kv(
    const float* __restrict__ A,      // (462, 768)
    const float* __restrict__ Wk,     // (768, 320)
    const float* __restrict__ Wv)     // (768, 320)
{
    constexpr int M = KVROWS, K = CD, NW = ID, NC = 2 * ID;
    __shared__ float As[16][64 + 4];
    __shared__ float Bs[16][64];

    const int tid = threadIdx.x;
    const int colBase = blockIdx.x * 64;          // in [0, 640)
    const int rowBase = blockIdx.y * 64;
    const float* Bm = (colBase < NW) ? Wk : Wv;
    const int cb = (colBase < NW) ? colBase : colBase - NW;

    const int tx = tid & 15, ty = tid >> 4;
    const int ar = tid >> 2;            // 0..63
    const int ac = (tid & 3) << 2;
    const int br = tid >> 4;
    const int bc = (tid & 15) << 2;

    float acc[4][4];
    #pragma unroll
    for (int i = 0; i < 4; i++)
        #pragma unroll
        for (int j = 0; j < 4; j++) acc[i][j] = 0.f;

    for (int k0 = 0; k0 < K; k0 += 16) {
        const int grow = rowBase + ar;
        float4 a = (grow < M) ? *(const float4*)&A[(size_t)grow * K + k0 + ac]
                              : make_float4(0.f, 0.f, 0.f, 0.f);
        float4 b = *(const float4*)&Bm[(size_t)(k0 + br) * NW + cb + bc];
        As[ac+0][ar] = a.x; As[ac+1][ar] = a.y; As[ac+2][ar] = a.z; As[ac+3][ar] = a.w;
        *(float4*)&Bs[br][bc] = b;
        __syncthreads();

        #pragma unroll
        for (int kk = 0; kk < 16; kk++) {
            float av[4], bv[4];
            #pragma unroll
            for (int i = 0; i < 4; i++) av[i] = As[kk][ty * 4 + i];
            #pragma unroll
            for (int j = 0; j < 4; j++) bv[j] = Bs[kk][tx * 4 + j];
            #pragma unroll
            for (int i = 0; i < 4; i++)
                #pragma unroll
                for (int j = 0; j < 4; j++) acc[i][j] += av[i] * bv[j];
        }
        __syncthreads();
    }

    #pragma unroll
    for (int i = 0; i < 4; i++) {
        const int r = rowBase + ty * 4 + i;
        if (r < M) {
            float4 v; v.x = acc[i][0]; v.y = acc[i][1]; v.z = acc[i][2]; v.w = acc[i][3];
            *(float4*)&g_kv[(size_t)r * NC + colBase + tx * 4] = v;
        }
    }
}

// =====================================================================
// Fused attention: per (b,h) block-tile of 128 query rows, 1 thread/row.
// - K,V (77x40 each) staged in smem, broadcast LDS.128 reads
// - scores in smem (stride 77 -> conflict-free: gcd(77,32)=1)
// - writes rear_sim (pre-softmax), softmax, token-2 reweight, PV, writes o
// =====================================================================
constexpr int ATTN_THREADS = 128;
constexpr size_t ATTN_SMEM = (size_t)(2 * CN * DH + ATTN_THREADS * CN) * sizeof(float); // 64064 B

__global__ void __launch_bounds__(ATTN_THREADS) attn_kernel(
    const float* __restrict__ q,    // (B*N, 320)
    float* __restrict__ sim,        // (B,H,N,77)
    float* __restrict__ o)          // (B*N, 320)
{
    extern __shared__ float smem[];
    float* Ks = smem;                       // [77][40]
    float* Vs = Ks + CN * DH;               // [77][40]
    float* Ss = Vs + CN * DH;               // [128][77]

    const int bh = blockIdx.y;
    const int b = bh >> 3;
    const int h = bh & 7;
    const int tid = threadIdx.x;

    // stage K, V for this (b, h)
    for (int i = tid; i < CN * DH; i += ATTN_THREADS) {
        const int j = i / DH, d = i - j * DH;
        const float* base = g_kv + (size_t)(b * CN + j) * (2 * ID) + h * DH + d;
        Ks[i] = base[0];
        Vs[i] = base[ID];
    }

    const int n = blockIdx.x * ATTN_THREADS + tid;
    const float* qrow = q + (size_t)(b * Nn + n) * ID + h * DH;
    float qr[DH];
    #pragma unroll
    for (int d = 0; d < DH; d += 4) {
        float4 t = *(const float4*)(qrow + d);
        qr[d] = t.x; qr[d+1] = t.y; qr[d+2] = t.z; qr[d+3] = t.w;
    }
    __syncthreads();

    float* srow = Ss + tid * CN;
    float m = -1e30f;
    for (int j = 0; j < CN; j++) {
        float a0 = 0.f, a1 = 0.f, a2 = 0.f, a3 = 0.f;
        const float* kr = Ks + j * DH;
        #pragma unroll
        for (int d = 0; d < DH; d += 4) {
            float4 k4 = *(const float4*)(kr + d);
            a0 += qr[d]   * k4.x; a1 += qr[d+1] * k4.y;
            a2 += qr[d+2] * k4.z; a3 += qr[d+3] * k4.w;
        }
        float v = ((a0 + a1) + (a2 + a3)) * SCALE;
        srow[j] = v;
        m = fmaxf(m, v);
    }

    // write pre-softmax sim (rear_sim)
    float* simRow = sim + ((size_t)bh * Nn + n) * CN;
    for (int j = 0; j < CN; j++) simRow[j] = srow[j];

    // softmax (unnormalized p kept in smem; divide by sum at the end)
    float sum = 0.f;
    for (int j = 0; j < CN; j++) {
        float e = __expf(srow[j] - m);
        srow[j] = e;
        sum += e;
    }
    const float inv = 1.f / sum;

    // cross-attention-control reweight on token 2 (post-softmax, pre-PV)
    float w = 1.f;
    if (b == 3) w = -2.f; else if (b == 5) w = 5.f;   // b==4 -> 1.0
    srow[2] *= w;

    float acc[DH];
    #pragma unroll
    for (int d = 0; d < DH; d++) acc[d] = 0.f;
    for (int j = 0; j < CN; j++) {
        const float p = srow[j];
        const float* vr = Vs + j * DH;
        #pragma unroll
        for (int d = 0; d < DH; d += 4) {
            float4 v4 = *(const float4*)(vr + d);
            acc[d]   += p * v4.x; acc[d+1] += p * v4.y;
            acc[d+2] += p * v4.z; acc[d+3] += p * v4.w;
        }
    }

    float* orow = o + (size_t)(b * Nn + n) * ID + h * DH;
    #pragma unroll
    for (int d = 0; d < DH; d += 4) {
        float4 t;
        t.x = acc[d] * inv; t.y = acc[d+1] * inv;
        t.z = acc[d+2] * inv; t.w = acc[d+3] * inv;
        *(float4*)(orow + d) = t;
    }
}

// =====================================================================
// launch
// =====================================================================
extern "C" void kernel_launch(void* const* d_in, const int* in_sizes, int n_in,
                              void* d_out, int out_size)
{
    const float* x   = (const float*)d_in[0];
    const float* ctx = (const float*)d_in[1];
    const float* Wq  = (const float*)d_in[2];
    const float* Wk  = (const float*)d_in[3];
    const float* Wv  = (const float*)d_in[4];
    const float* Wo  = (const float*)d_in[5];
    const float* bo  = (const float*)d_in[6];
    // d_in[7] = time (unused: reweight always applies for time >= 0)

    float* out = (float*)d_out;                       // (B, N, 320)
    float* sim = out + (size_t)Bn * Nn * QD;          // (B, H, N, 77)

    float *qp = nullptr, *op = nullptr;
    cudaGetSymbolAddress((void**)&qp, g_q);
    cudaGetSymbolAddress((void**)&op, g_o);

    cudaFuncSetAttribute(attn_kernel, cudaFuncAttributeMaxDynamicSharedMemorySize,
                         (int)ATTN_SMEM);

    // K & V projections (one launch), independent of Q projection
    sgemm_kv<<<dim3((2 * ID) / 64, (KVROWS + 63) / 64), 256>>>(ctx, Wk, Wv);

    // Q projection
    sgemm_big<false><<<dim3(ID / 64, MROWS / 128), 256>>>(x, Wq, nullptr, qp,
                                                          MROWS, ID, QD);

    // fused sim + rear_sim write + softmax + reweight + PV
    attn_kernel<<<dim3(Nn / ATTN_THREADS, Bn * Hh), ATTN_THREADS, ATTN_SMEM>>>(qp, sim, op);

    // output projection + bias
    sgemm_big<true><<<dim3(QD / 64, MROWS / 128), 256>>>(op, Wo, bo, out,
                                                         MROWS, QD, ID);
}

// round 3
// speedup vs baseline: 1.2782x; 1.2782x over previous
#include <cuda_runtime.h>
#include <cstdint>
#include <cstddef>

// ---------------- problem constants ----------------
constexpr int Bn  = 6;
constexpr int Nn  = 4096;
constexpr int QD  = 320;
constexpr int CN  = 77;
constexpr int CD  = 768;
constexpr int Hh  = 8;
constexpr int DH  = 40;
constexpr int ID  = Hh * DH;          // 320 inner dim
constexpr float SCALE = 0.15811388300841897f; // 40^-0.5

constexpr int MROWS = Bn * Nn;        // 24576
constexpr int KVROWS = Bn * CN;       // 462

// ---------------- scratch (static device memory; no allocs allowed) ------
__device__ float g_q [ (size_t)MROWS * ID ];     // q projection, (B*N, 320)
__device__ float g_o [ (size_t)MROWS * ID ];     // attn@v merged heads, (B*N, 320)
__device__ float g_kv[ (size_t)KVROWS * 2 * ID ];// (B*CN, 640): cols [0,320)=K, [320,640)=V

// =====================================================================
// TF32 tensor-core GEMM: C(24576x320) = A(24576x320) @ W(320x320) (+bias)
// mma.sync.m16n8k8 tf32. BM=128, BN=64, BK=32, 256 threads.
// Warp layout 4(M) x 2(N); warp tile 32x32 = 2 m16-tiles x 4 n8-tiles.
// SMEM: As[128][36] (stride%32==4 -> fragment bank == laneid, conflict-free)
//       Bs[32][68]  (k-major, stride%32==4 -> conflict-free fragment loads)
// cvt.rna.tf32.f32 applied once at SMEM store time (u32 dst per PTX spec).
// =====================================================================
__device__ __forceinline__ uint32_t f2tf32(float f) {
    uint32_t r;
    asm("cvt.rna.tf32.f32 %0, %1;" : "=r"(r) : "f"(f));
    return r;
}
__device__ __forceinline__ uint4 tf32x4(float4 v) {
    uint4 r;
    r.x = f2tf32(v.x); r.y = f2tf32(v.y);
    r.z = f2tf32(v.z); r.w = f2tf32(v.w);
    return r;
}

template<bool BIAS>
__global__ void __launch_bounds__(256) gemm_tf32(
    const float* __restrict__ A,      // (24576, 320)
    const float* __restrict__ W,      // (320, 320)
    const float* __restrict__ bias,   // (320) or null
    float* __restrict__ C)            // (24576, 320)
{
    constexpr int Nc = 320, K = 320;
    constexpr int BM = 128, BN = 64, BK = 32;
    constexpr int ASTRIDE = 36;   // 32 + 4 pad: (36 % 32) == 4
    constexpr int BSTRIDE = 68;   // 64 + 4 pad: (68 % 32) == 4

    __shared__ uint32_t As[BM][ASTRIDE];
    __shared__ uint32_t Bs[BK][BSTRIDE];

    const int tid  = threadIdx.x;
    const int lane = tid & 31;
    const int wid  = tid >> 5;
    const int warpM = wid & 3;        // 0..3  -> 32-row slice
    const int warpN = wid >> 2;       // 0..1  -> 32-col slice
    const int g = lane >> 2;          // groupID 0..7
    const int t = lane & 3;           // threadID-in-group 0..3

    const int rowBase = blockIdx.y * BM;
    const int colBase = blockIdx.x * BN;

    // global->smem copy maps
    const int arow = tid >> 1;               // 0..127
    const int acol = (tid & 1) * 16;         // 0 or 16; 4 float4 each
    const int brow = tid >> 3;               // 0..31
    const int bcol = (tid & 7) * 8;          // 0..56; 2 float4 each

    const float* aPtr = A + (size_t)(rowBase + arow) * K + acol;
    const float* bPtr = W + (size_t)brow * Nc + colBase + bcol;

    float4 aR[4], bR[2];
    #pragma unroll
    for (int i = 0; i < 4; i++) aR[i] = *(const float4*)(aPtr + 4 * i);
    bR[0] = *(const float4*)(bPtr);
    bR[1] = *(const float4*)(bPtr + 4);

    float4 acc[2][4];
    #pragma unroll
    for (int m = 0; m < 2; m++)
        #pragma unroll
        for (int nt = 0; nt < 4; nt++)
            acc[m][nt] = make_float4(0.f, 0.f, 0.f, 0.f);

    for (int k0 = 0; k0 < K; k0 += BK) {
        // store current tile (tf32-rounded bit patterns)
        #pragma unroll
        for (int i = 0; i < 4; i++)
            *(uint4*)&As[arow][acol + 4 * i] = tf32x4(aR[i]);
        *(uint4*)&Bs[brow][bcol]     = tf32x4(bR[0]);
        *(uint4*)&Bs[brow][bcol + 4] = tf32x4(bR[1]);
        __syncthreads();

        // prefetch next tile while computing
        if (k0 + BK < K) {
            #pragma unroll
            for (int i = 0; i < 4; i++)
                aR[i] = *(const float4*)(aPtr + k0 + BK + 4 * i);
            bR[0] = *(const float4*)(bPtr + (size_t)(k0 + BK) * Nc);
            bR[1] = *(const float4*)(bPtr + (size_t)(k0 + BK) * Nc + 4);
        }

        #pragma unroll
        for (int kk = 0; kk < 4; kk++) {
            const int kc = kk * 8;
            uint32_t a[2][4], b[4][2];
            #pragma unroll
            for (int m = 0; m < 2; m++) {
                const int r0 = warpM * 32 + m * 16 + g;
                a[m][0] = As[r0    ][kc + t    ];
                a[m][1] = As[r0 + 8][kc + t    ];
                a[m][2] = As[r0    ][kc + t + 4];
                a[m][3] = As[r0 + 8][kc + t + 4];
            }
            #pragma unroll
            for (int nt = 0; nt < 4; nt++) {
                const int n0 = warpN * 32 + nt * 8 + g;
                b[nt][0] = Bs[kc + t    ][n0];
                b[nt][1] = Bs[kc + t + 4][n0];
            }
            #pragma unroll
            for (int m = 0; m < 2; m++)
                #pragma unroll
                for (int nt = 0; nt < 4; nt++) {
                    asm volatile(
                        "mma.sync.aligned.m16n8k8.row.col.f32.tf32.tf32.f32 "
                        "{%0,%1,%2,%3}, {%4,%5,%6,%7}, {%8,%9}, {%0,%1,%2,%3};\n"
                        : "+f"(acc[m][nt].x), "+f"(acc[m][nt].y),
                          "+f"(acc[m][nt].z), "+f"(acc[m][nt].w)
                        : "r"(a[m][0]), "r"(a[m][1]), "r"(a[m][2]), "r"(a[m][3]),
                          "r"(b[nt][0]), "r"(b[nt][1]));
                }
        }
        __syncthreads();
    }

    // epilogue
    #pragma unroll
    for (int m = 0; m < 2; m++) {
        const int row = rowBase + warpM * 32 + m * 16 + g;
        #pragma unroll
        for (int nt = 0; nt < 4; nt++) {
            const int col = colBase + warpN * 32 + nt * 8 + 2 * t;
            float b0 = 0.f, b1 = 0.f;
            if (BIAS) { b0 = bias[col]; b1 = bias[col + 1]; }
            float2 lo, hi;
            lo.x = acc[m][nt].x + b0; lo.y = acc[m][nt].y + b1;
            hi.x = acc[m][nt].z + b0; hi.y = acc[m][nt].w + b1;
            *(float2*)&C[(size_t)row * Nc + col]       = lo;
            *(float2*)&C[(size_t)(row + 8) * Nc + col] = hi;
        }
    }
}

// =====================================================================
// K/V projection in ONE launch: C(462x640) where cols [0,320)=ctx@Wk,
// [320,640)=ctx@Wv. 64x64 tile, BK=16, 256 threads, 4x4 microtile.
// =====================================================================
__global__ void __launch_bounds__(256) sgemm_kv(
    const float* __restrict__ A,      // (462, 768)
    const float* __restrict__ Wk,     // (768, 320)
    const float* __restrict__ Wv)     // (768, 320)
{
    constexpr int M = KVROWS, K = CD, NW = ID, NC = 2 * ID;
    __shared__ float As[16][64 + 4];
    __shared__ float Bs[16][64];

    const int tid = threadIdx.x;
    const int colBase = blockIdx.x * 64;          // in [0, 640)
    const int rowBase = blockIdx.y * 64;
    const float* Bm = (colBase < NW) ? Wk : Wv;
    const int cb = (colBase < NW) ? colBase : colBase - NW;

    const int tx = tid & 15, ty = tid >> 4;
    const int ar = tid >> 2;
    const int ac = (tid & 3) << 2;
    const int br = tid >> 4;
    const int bc = (tid & 15) << 2;

    float acc[4][4];
    #pragma unroll
    for (int i = 0; i < 4; i++)
        #pragma unroll
        for (int j = 0; j < 4; j++) acc[i][j] = 0.f;

    for (int k0 = 0; k0 < K; k0 += 16) {
        const int grow = rowBase + ar;
        float4 a = (grow < M) ? *(const float4*)&A[(size_t)grow * K + k0 + ac]
                              : make_float4(0.f, 0.f, 0.f, 0.f);
        float4 b = *(const float4*)&Bm[(size_t)(k0 + br) * NW + cb + bc];
        As[ac+0][ar] = a.x; As[ac+1][ar] = a.y; As[ac+2][ar] = a.z; As[ac+3][ar] = a.w;
        *(float4*)&Bs[br][bc] = b;
        __syncthreads();

        #pragma unroll
        for (int kk = 0; kk < 16; kk++) {
            float av[4], bv[4];
            #pragma unroll
            for (int i = 0; i < 4; i++) av[i] = As[kk][ty * 4 + i];
            #pragma unroll
            for (int j = 0; j < 4; j++) bv[j] = Bs[kk][tx * 4 + j];
            #pragma unroll
            for (int i = 0; i < 4; i++)
                #pragma unroll
                for (int j = 0; j < 4; j++) acc[i][j] += av[i] * bv[j];
        }
        __syncthreads();
    }

    #pragma unroll
    for (int i = 0; i < 4; i++) {
        const int r = rowBase + ty * 4 + i;
        if (r < M) {
            float4 v; v.x = acc[i][0]; v.y = acc[i][1]; v.z = acc[i][2]; v.w = acc[i][3];
            *(float4*)&g_kv[(size_t)r * NC + colBase + tx * 4] = v;
        }
    }
}

// =====================================================================
// Fused attention: per (b,h) block-tile of 128 query rows, 1 thread/row.
// =====================================================================
constexpr int ATTN_THREADS = 128;
constexpr size_t ATTN_SMEM = (size_t)(2 * CN * DH + ATTN_THREADS * CN) * sizeof(float); // 64064 B

__global__ void __launch_bounds__(ATTN_THREADS) attn_kernel(
    const float* __restrict__ q,    // (B*N, 320)
    float* __restrict__ sim,        // (B,H,N,77)
    float* __restrict__ o)          // (B*N, 320)
{
    extern __shared__ float smem[];
    float* Ks = smem;                       // [77][40]
    float* Vs = Ks + CN * DH;               // [77][40]
    float* Ss = Vs + CN * DH;               // [128][77]

    const int bh = blockIdx.y;
    const int b = bh >> 3;
    const int h = bh & 7;
    const int tid = threadIdx.x;

    for (int i = tid; i < CN * DH; i += ATTN_THREADS) {
        const int j = i / DH, d = i - j * DH;
        const float* base = g_kv + (size_t)(b * CN + j) * (2 * ID) + h * DH + d;
        Ks[i] = base[0];
        Vs[i] = base[ID];
    }

    const int n = blockIdx.x * ATTN_THREADS + tid;
    const float* qrow = q + (size_t)(b * Nn + n) * ID + h * DH;
    float qr[DH];
    #pragma unroll
    for (int d = 0; d < DH; d += 4) {
        float4 tq = *(const float4*)(qrow + d);
        qr[d] = tq.x; qr[d+1] = tq.y; qr[d+2] = tq.z; qr[d+3] = tq.w;
    }
    __syncthreads();

    float* srow = Ss + tid * CN;
    float m = -1e30f;
    for (int j = 0; j < CN; j++) {
        float a0 = 0.f, a1 = 0.f, a2 = 0.f, a3 = 0.f;
        const float* kr = Ks + j * DH;
        #pragma unroll
        for (int d = 0; d < DH; d += 4) {
            float4 k4 = *(const float4*)(kr + d);
            a0 += qr[d]   * k4.x; a1 += qr[d+1] * k4.y;
            a2 += qr[d+2] * k4.z; a3 += qr[d+3] * k4.w;
        }
        float v = ((a0 + a1) + (a2 + a3)) * SCALE;
        srow[j] = v;
        m = fmaxf(m, v);
    }

    float* simRow = sim + ((size_t)bh * Nn + n) * CN;
    for (int j = 0; j < CN; j++) simRow[j] = srow[j];

    float sum = 0.f;
    for (int j = 0; j < CN; j++) {
        float e = __expf(srow[j] - m);
        srow[j] = e;
        sum += e;
    }
    const float inv = 1.f / sum;

    float w = 1.f;
    if (b == 3) w = -2.f; else if (b == 5) w = 5.f;   // b==4 -> 1.0
    srow[2] *= w;

    float acc[DH];
    #pragma unroll
    for (int d = 0; d < DH; d++) acc[d] = 0.f;
    for (int j = 0; j < CN; j++) {
        const float p = srow[j];
        const float* vr = Vs + j * DH;
        #pragma unroll
        for (int d = 0; d < DH; d += 4) {
            float4 v4 = *(const float4*)(vr + d);
            acc[d]   += p * v4.x; acc[d+1] += p * v4.y;
            acc[d+2] += p * v4.z; acc[d+3] += p * v4.w;
        }
    }

    float* orow = o + (size_t)(b * Nn + n) * ID + h * DH;
    #pragma unroll
    for (int d = 0; d < DH; d += 4) {
        float4 tq;
        tq.x = acc[d] * inv; tq.y = acc[d+1] * inv;
        tq.z = acc[d+2] * inv; tq.w = acc[d+3] * inv;
        *(float4*)(orow + d) = tq;
    }
}

// =====================================================================
// launch
// =====================================================================
extern "C" void kernel_launch(void* const* d_in, const int* in_sizes, int n_in,
                              void* d_out, int out_size)
{
    const float* x   = (const float*)d_in[0];
    const float* ctx = (const float*)d_in[1];
    const float* Wq  = (const float*)d_in[2];
    const float* Wk  = (const float*)d_in[3];
    const float* Wv  = (const float*)d_in[4];
    const float* Wo  = (const float*)d_in[5];
    const float* bo  = (const float*)d_in[6];
    // d_in[7] = time (unused: reweight always applies for time >= 0)

    float* out = (float*)d_out;                       // (B, N, 320)
    float* sim = out + (size_t)Bn * Nn * QD;          // (B, H, N, 77)

    float *qp = nullptr, *op = nullptr;
    cudaGetSymbolAddress((void**)&qp, g_q);
    cudaGetSymbolAddress((void**)&op, g_o);

    cudaFuncSetAttribute(attn_kernel, cudaFuncAttributeMaxDynamicSharedMemorySize,
                         (int)ATTN_SMEM);

    // K & V projections (one launch)
    sgemm_kv<<<dim3((2 * ID) / 64, (KVROWS + 63) / 64), 256>>>(ctx, Wk, Wv);

    // Q projection (tf32 tensor cores)
    gemm_tf32<false><<<dim3(320 / 64, MROWS / 128), 256>>>(x, Wq, nullptr, qp);

    // fused sim + rear_sim write + softmax + reweight + PV
    attn_kernel<<<dim3(Nn / ATTN_THREADS, Bn * Hh), ATTN_THREADS, ATTN_SMEM>>>(qp, sim, op);

    // output projection + bias (tf32 tensor cores)
    gemm_tf32<true><<<dim3(320 / 64, MROWS / 128), 256>>>(op, Wo, bo, out);
}

// round 6
// speedup vs baseline: 1.7118x; 1.3392x over previous
#include <cuda_runtime.h>
#include <cstdint>
#include <cstddef>

// ---------------- problem constants ----------------
constexpr int Bn  = 6;
constexpr int Nn  = 4096;
constexpr int QD  = 320;
constexpr int CN  = 77;
constexpr int CD  = 768;
constexpr int Hh  = 8;
constexpr int DH  = 40;
constexpr int ID  = Hh * DH;          // 320 inner dim
constexpr float SCALE = 0.15811388300841897f; // 40^-0.5

constexpr int MROWS = Bn * Nn;        // 24576
constexpr int KVROWS = Bn * CN;       // 462

// single extern shared symbol (attn only)
extern __shared__ char smem_raw[];

// ---------------- scratch (static device memory; no allocs allowed) ------
__device__ float g_q [ (size_t)MROWS * ID ];     // q projection, (B*N, 320)
__device__ float g_o [ (size_t)MROWS * ID ];     // attn@v merged heads, (B*N, 320)
__device__ float g_kv[ (size_t)KVROWS * 2 * ID ];// (B*CN, 640): [0,320)=K, [320,640)=V

// ---------------- helpers ----------------
__device__ __forceinline__ uint32_t f2tf32(float f) {
    uint32_t r;
    asm("cvt.rna.tf32.f32 %0, %1;" : "=r"(r) : "f"(f));
    return r;
}
__device__ __forceinline__ uint4 tf32x4(float4 v) {
    uint4 r;
    r.x = f2tf32(v.x); r.y = f2tf32(v.y);
    r.z = f2tf32(v.z); r.w = f2tf32(v.w);
    return r;
}
// FFMA-only exp (x <= 0 expected; relative error ~2.5e-6)
__device__ __forceinline__ float fast_exp(float x) {
    x = fmaxf(x, -60.f);
    float y = x * 1.4426950408889634f;        // x * log2(e)
    int   n = __float2int_rn(y);
    float f = y - (float)n;
    float t = f * 0.6931471805599453f;        // f * ln2, |t| <= 0.3466
    float p = 8.3333333333e-3f;               // 1/120
    p = fmaf(p, t, 4.1666666667e-2f);         // 1/24
    p = fmaf(p, t, 1.6666666667e-1f);         // 1/6
    p = fmaf(p, t, 0.5f);
    p = fmaf(p, t, 1.0f);
    p = fmaf(p, t, 1.0f);
    return __int_as_float(__float_as_int(p) + (n << 23));
}

#define MMA_TF32(acc, a0, a1, a2, a3, b0, b1)                                   \
    asm volatile(                                                               \
        "mma.sync.aligned.m16n8k8.row.col.f32.tf32.tf32.f32 "                   \
        "{%0,%1,%2,%3}, {%4,%5,%6,%7}, {%8,%9}, {%0,%1,%2,%3};\n"               \
        : "+f"(acc[0]), "+f"(acc[1]), "+f"(acc[2]), "+f"(acc[3])                \
        : "r"(a0), "r"(a1), "r"(a2), "r"(a3), "r"(b0), "r"(b1))

// =====================================================================
// TF32 tensor-core GEMM (mma.sync): C(24576x320) = A @ W (+bias)
// BM=128, BN=64, BK=32, 256 threads; warp 32x32. (R3-proven, 83us)
// =====================================================================
template<bool BIAS>
__global__ void __launch_bounds__(256) gemm_tf32(
    const float* __restrict__ A,      // (24576, 320)
    const float* __restrict__ W,      // (320, 320)
    const float* __restrict__ bias,   // (320) or null
    float* __restrict__ C)            // (24576, 320)
{
    constexpr int Nc = 320, K = 320;
    constexpr int BM = 128, BN = 64, BK = 32;
    constexpr int ASTRIDE = 36;   // (36 % 32) == 4 -> conflict-free fragments
    constexpr int BSTRIDE = 68;   // (68 % 32) == 4

    __shared__ uint32_t As[BM][ASTRIDE];
    __shared__ uint32_t Bs[BK][BSTRIDE];

    const int tid  = threadIdx.x;
    const int lane = tid & 31;
    const int wid  = tid >> 5;
    const int warpM = wid & 3;
    const int warpN = wid >> 2;
    const int g = lane >> 2;
    const int t = lane & 3;

    const int rowBase = blockIdx.y * BM;
    const int colBase = blockIdx.x * BN;

    const int arow = tid >> 1;
    const int acol = (tid & 1) * 16;
    const int brow = tid >> 3;
    const int bcol = (tid & 7) * 8;

    const float* aPtr = A + (size_t)(rowBase + arow) * K + acol;
    const float* bPtr = W + (size_t)brow * Nc + colBase + bcol;

    float4 aR[4], bR[2];
    #pragma unroll
    for (int i = 0; i < 4; i++) aR[i] = *(const float4*)(aPtr + 4 * i);
    bR[0] = *(const float4*)(bPtr);
    bR[1] = *(const float4*)(bPtr + 4);

    float acc[2][4][4];
    #pragma unroll
    for (int m = 0; m < 2; m++)
        #pragma unroll
        for (int nt = 0; nt < 4; nt++)
            #pragma unroll
            for (int r = 0; r < 4; r++) acc[m][nt][r] = 0.f;

    for (int k0 = 0; k0 < K; k0 += BK) {
        #pragma unroll
        for (int i = 0; i < 4; i++)
            *(uint4*)&As[arow][acol + 4 * i] = tf32x4(aR[i]);
        *(uint4*)&Bs[brow][bcol]     = tf32x4(bR[0]);
        *(uint4*)&Bs[brow][bcol + 4] = tf32x4(bR[1]);
        __syncthreads();

        if (k0 + BK < K) {
            #pragma unroll
            for (int i = 0; i < 4; i++)
                aR[i] = *(const float4*)(aPtr + k0 + BK + 4 * i);
            bR[0] = *(const float4*)(bPtr + (size_t)(k0 + BK) * Nc);
            bR[1] = *(const float4*)(bPtr + (size_t)(k0 + BK) * Nc + 4);
        }

        #pragma unroll
        for (int kk = 0; kk < 4; kk++) {
            const int kc = kk * 8;
            uint32_t a[2][4], b[4][2];
            #pragma unroll
            for (int m = 0; m < 2; m++) {
                const int r0 = warpM * 32 + m * 16 + g;
                a[m][0] = As[r0    ][kc + t    ];
                a[m][1] = As[r0 + 8][kc + t    ];
                a[m][2] = As[r0    ][kc + t + 4];
                a[m][3] = As[r0 + 8][kc + t + 4];
            }
            #pragma unroll
            for (int nt = 0; nt < 4; nt++) {
                const int n0 = warpN * 32 + nt * 8 + g;
                b[nt][0] = Bs[kc + t    ][n0];
                b[nt][1] = Bs[kc + t + 4][n0];
            }
            #pragma unroll
            for (int m = 0; m < 2; m++)
                #pragma unroll
                for (int nt = 0; nt < 4; nt++)
                    MMA_TF32(acc[m][nt], a[m][0], a[m][1], a[m][2], a[m][3],
                             b[nt][0], b[nt][1]);
        }
        __syncthreads();
    }

    #pragma unroll
    for (int m = 0; m < 2; m++) {
        const int row = rowBase + warpM * 32 + m * 16 + g;
        #pragma unroll
        for (int nt = 0; nt < 4; nt++) {
            const int col = colBase + warpN * 32 + nt * 8 + 2 * t;
            float b0 = 0.f, b1 = 0.f;
            if (BIAS) { b0 = bias[col]; b1 = bias[col + 1]; }
            float2 lo, hi;
            lo.x = acc[m][nt][0] + b0; lo.y = acc[m][nt][1] + b1;
            hi.x = acc[m][nt][2] + b0; hi.y = acc[m][nt][3] + b1;
            *(float2*)&C[(size_t)row * Nc + col]       = lo;
            *(float2*)&C[(size_t)(row + 8) * Nc + col] = hi;
        }
    }
}

// =====================================================================
// K/V projection in ONE launch (fp32 FFMA; tiny: 462x640x768)
// =====================================================================
__global__ void __launch_bounds__(256) sgemm_kv(
    const float* __restrict__ A,      // (462, 768)
    const float* __restrict__ Wk,     // (768, 320)
    const float* __restrict__ Wv)     // (768, 320)
{
    constexpr int M = KVROWS, K = CD, NW = ID, NC = 2 * ID;
    __shared__ float As[16][64 + 4];
    __shared__ float Bs[16][64];

    const int tid = threadIdx.x;
    const int colBase = blockIdx.x * 64;
    const int rowBase = blockIdx.y * 64;
    const float* Bm = (colBase < NW) ? Wk : Wv;
    const int cb = (colBase < NW) ? colBase : colBase - NW;

    const int tx = tid & 15, ty = tid >> 4;
    const int ar = tid >> 2;
    const int ac = (tid & 3) << 2;
    const int br = tid >> 4;
    const int bc = (tid & 15) << 2;

    float acc[4][4];
    #pragma unroll
    for (int i = 0; i < 4; i++)
        #pragma unroll
        for (int j = 0; j < 4; j++) acc[i][j] = 0.f;

    for (int k0 = 0; k0 < K; k0 += 16) {
        const int grow = rowBase + ar;
        float4 a = (grow < M) ? *(const float4*)&A[(size_t)grow * K + k0 + ac]
                              : make_float4(0.f, 0.f, 0.f, 0.f);
        float4 b = *(const float4*)&Bm[(size_t)(k0 + br) * NW + cb + bc];
        As[ac+0][ar] = a.x; As[ac+1][ar] = a.y; As[ac+2][ar] = a.z; As[ac+3][ar] = a.w;
        *(float4*)&Bs[br][bc] = b;
        __syncthreads();

        #pragma unroll
        for (int kk = 0; kk < 16; kk++) {
            float av[4], bv[4];
            #pragma unroll
            for (int i = 0; i < 4; i++) av[i] = As[kk][ty * 4 + i];
            #pragma unroll
            for (int j = 0; j < 4; j++) bv[j] = Bs[kk][tx * 4 + j];
            #pragma unroll
            for (int i = 0; i < 4; i++)
                #pragma unroll
                for (int j = 0; j < 4; j++) acc[i][j] += av[i] * bv[j];
        }
        __syncthreads();
    }

    #pragma unroll
    for (int i = 0; i < 4; i++) {
        const int r = rowBase + ty * 4 + i;
        if (r < M) {
            float4 v; v.x = acc[i][0]; v.y = acc[i][1]; v.z = acc[i][2]; v.w = acc[i][3];
            *(float4*)&g_kv[(size_t)r * NC + colBase + tx * 4] = v;
        }
    }
}

// =====================================================================
// Tensor-core fused attention. Per block: one (b,h), 128 query rows.
//   1. stage Q[128][40], K[80][40], V[80][40] (tf32-rounded, rows 77..79 zero)
//   2. S = QK^T * SCALE via mma.sync -> Ss[128][84]
//   3. coalesced rear_sim write from Ss
//   4. softmax (FFMA exp), token-2 reweight, P (tf32) in-place in Ss
//   5. O = P V via mma.sync, * inv(sum), write g_o
// 256 threads (8 warps).
// =====================================================================
constexpr int SS_STRIDE = 84;   // 84 % 32 == 20 -> A-fragment conflict-free
constexpr int ATTN_SMEM_B =
    (128 * DH + 80 * DH + 80 * DH + 128 * SS_STRIDE + 128) * 4;  // 89,600 B

__global__ void __launch_bounds__(256) attn_kernel(
    const float* __restrict__ q,    // (B*N, 320)
    float* __restrict__ sim,        // (B,H,N,77)
    float* __restrict__ o)          // (B*N, 320)
{
    float* Qs   = (float*)smem_raw;            // [128][40]
    float* Ks   = Qs + 128 * DH;               // [80][40]
    float* Vs   = Ks + 80 * DH;                // [80][40]
    float* Ss   = Vs + 80 * DH;                // [128][84]
    float* Sinv = Ss + 128 * SS_STRIDE;        // [128]

    const int bh = blockIdx.y;
    const int b = bh >> 3;
    const int h = bh & 7;
    const int tid  = threadIdx.x;
    const int lane = tid & 31;
    const int wid  = tid >> 5;
    const int g = lane >> 2;
    const int t = lane & 3;
    const int nBase = blockIdx.x * 128;

    // ---- stage Q (tf32-rounded) ----
    {
        const float* qb = q + ((size_t)(b * Nn + nBase)) * ID + h * DH;
        #pragma unroll
        for (int i = 0; i < 5; i++) {
            const int idx = tid + 256 * i;        // 0..1279 float4s
            const int r = idx / 10, c4 = (idx - r * 10) * 4;
            float4 v = *(const float4*)(qb + (size_t)r * ID + c4);
            *(uint4*)&Qs[r * DH + c4] = tf32x4(v);
        }
    }
    // ---- stage K, V (tf32-rounded); zero pad rows 77..79 ----
    for (int idx = tid; idx < CN * 10; idx += 256) {   // 770 float4s each
        const int r = idx / 10, c4 = (idx - r * 10) * 4;
        const float* base = g_kv + (size_t)(b * CN + r) * (2 * ID) + h * DH + c4;
        *(uint4*)&Ks[r * DH + c4] = tf32x4(*(const float4*)(base));
        *(uint4*)&Vs[r * DH + c4] = tf32x4(*(const float4*)(base + ID));
    }
    if (tid < 120) {                                    // 3 pad rows x 40
        Ks[CN * DH + tid] = 0.f;
        Vs[CN * DH + tid] = 0.f;
    }
    __syncthreads();

    // ---- QK^T: warps wm(0..3) x wn(0..1); warp tile 32 rows x 40 cols ----
    {
        const int wm = wid & 3;
        const int wn = wid >> 2;
        float acc[2][5][4];
        #pragma unroll
        for (int m = 0; m < 2; m++)
            #pragma unroll
            for (int nt = 0; nt < 5; nt++)
                #pragma unroll
                for (int r = 0; r < 4; r++) acc[m][nt][r] = 0.f;

        #pragma unroll
        for (int ks = 0; ks < 5; ks++) {
            const int kc = ks * 8;
            uint32_t a[2][4], bfr[5][2];
            #pragma unroll
            for (int m = 0; m < 2; m++) {
                const int r0 = wm * 32 + m * 16 + g;
                a[m][0] = __float_as_uint(Qs[(r0    ) * DH + kc + t    ]);
                a[m][1] = __float_as_uint(Qs[(r0 + 8) * DH + kc + t    ]);
                a[m][2] = __float_as_uint(Qs[(r0    ) * DH + kc + t + 4]);
                a[m][3] = __float_as_uint(Qs[(r0 + 8) * DH + kc + t + 4]);
            }
            #pragma unroll
            for (int nt = 0; nt < 5; nt++) {
                const int n0 = wn * 40 + nt * 8 + g;
                bfr[nt][0] = __float_as_uint(Ks[n0 * DH + kc + t    ]);
                bfr[nt][1] = __float_as_uint(Ks[n0 * DH + kc + t + 4]);
            }
            #pragma unroll
            for (int m = 0; m < 2; m++)
                #pragma unroll
                for (int nt = 0; nt < 5; nt++)
                    MMA_TF32(acc[m][nt], a[m][0], a[m][1], a[m][2], a[m][3],
                             bfr[nt][0], bfr[nt][1]);
        }
        // store scaled S to Ss
        #pragma unroll
        for (int m = 0; m < 2; m++) {
            const int r0 = wm * 32 + m * 16 + g;
            #pragma unroll
            for (int nt = 0; nt < 5; nt++) {
                const int c = wn * 40 + nt * 8 + 2 * t;
                float2 lo, hi;
                lo.x = acc[m][nt][0] * SCALE; lo.y = acc[m][nt][1] * SCALE;
                hi.x = acc[m][nt][2] * SCALE; hi.y = acc[m][nt][3] * SCALE;
                *(float2*)&Ss[(r0    ) * SS_STRIDE + c] = lo;
                *(float2*)&Ss[(r0 + 8) * SS_STRIDE + c] = hi;
            }
        }
    }
    __syncthreads();

    // ---- rear_sim write (coalesced): warp w -> rows 16w..16w+15 ----
    {
        #pragma unroll
        for (int rr = 0; rr < 16; rr++) {
            const int r = wid * 16 + rr;
            float* dst = sim + ((size_t)bh * Nn + nBase + r) * CN;
            const float* src = Ss + r * SS_STRIDE;
            dst[lane]      = src[lane];
            dst[lane + 32] = src[lane + 32];
            if (lane < CN - 64) dst[lane + 64] = src[lane + 64];
        }
    }
    __syncthreads();

    // ---- softmax: thread pair (2r, 2r+1) handles row r ----
    {
        const int r = tid >> 1;
        const int half = tid & 1;
        float* srow = Ss + r * SS_STRIDE;
        const int j0 = half ? 40 : 0;
        const int j1 = half ? CN : 40;

        float m = -1e30f;
        for (int j = j0; j < j1; j++) m = fmaxf(m, srow[j]);
        m = fmaxf(m, __shfl_xor_sync(0xFFFFFFFF, m, 1));

        float sum = 0.f;
        for (int j = j0; j < j1; j++) {
            float e = fast_exp(srow[j] - m);
            sum += e;
            srow[j] = e;
        }
        sum += __shfl_xor_sync(0xFFFFFFFF, sum, 1);

        if (!half) {
            Sinv[r] = 1.f / sum;
            // post-softmax token-2 reweight (b==3 -> -2, b==5 -> 5)
            float w = 1.f;
            if (b == 3) w = -2.f; else if (b == 5) w = 5.f;
            srow[2] *= w;
        }
    }
    __syncthreads();
    // tf32-round P in place (pads 77..79 are exact zeros already)
    for (int i = tid; i < 128 * CN; i += 256) {
        const int r = i / CN, c = i - r * CN;
        float* p = &Ss[r * SS_STRIDE + c];
        *p = __uint_as_float(f2tf32(*p));
    }
    __syncthreads();

    // ---- P V: warp w -> 16 rows; N=40 (5 n-tiles); K=80 (10 k-steps) ----
    {
        const int m0 = wid * 16;
        float acc[5][4];
        #pragma unroll
        for (int nt = 0; nt < 5; nt++)
            #pragma unroll
            for (int r = 0; r < 4; r++) acc[nt][r] = 0.f;

        #pragma unroll
        for (int ks = 0; ks < 10; ks++) {
            const int kc = ks * 8;
            uint32_t a[4], bfr[5][2];
            a[0] = __float_as_uint(Ss[(m0 + g    ) * SS_STRIDE + kc + t    ]);
            a[1] = __float_as_uint(Ss[(m0 + g + 8) * SS_STRIDE + kc + t    ]);
            a[2] = __float_as_uint(Ss[(m0 + g    ) * SS_STRIDE + kc + t + 4]);
            a[3] = __float_as_uint(Ss[(m0 + g + 8) * SS_STRIDE + kc + t + 4]);
            #pragma unroll
            for (int nt = 0; nt < 5; nt++) {
                const int n0 = nt * 8 + g;
                bfr[nt][0] = __float_as_uint(Vs[(kc + t    ) * DH + n0]);
                bfr[nt][1] = __float_as_uint(Vs[(kc + t + 4) * DH + n0]);
            }
            #pragma unroll
            for (int nt = 0; nt < 5; nt++)
                MMA_TF32(acc[nt], a[0], a[1], a[2], a[3], bfr[nt][0], bfr[nt][1]);
        }

        const int r0 = m0 + g;
        const float inv0 = Sinv[r0];
        const float inv1 = Sinv[r0 + 8];
        float* o0 = o + ((size_t)(b * Nn + nBase + r0    )) * ID + h * DH;
        float* o1 = o + ((size_t)(b * Nn + nBase + r0 + 8)) * ID + h * DH;
        #pragma unroll
        for (int nt = 0; nt < 5; nt++) {
            const int c = nt * 8 + 2 * t;
            float2 lo, hi;
            lo.x = acc[nt][0] * inv0; lo.y = acc[nt][1] * inv0;
            hi.x = acc[nt][2] * inv1; hi.y = acc[nt][3] * inv1;
            *(float2*)(o0 + c) = lo;
            *(float2*)(o1 + c) = hi;
        }
    }
}

// =====================================================================
// launch
// =====================================================================
extern "C" void kernel_launch(void* const* d_in, const int* in_sizes, int n_in,
                              void* d_out, int out_size)
{
    const float* x   = (const float*)d_in[0];
    const float* ctx = (const float*)d_in[1];
    const float* Wq  = (const float*)d_in[2];
    const float* Wk  = (const float*)d_in[3];
    const float* Wv  = (const float*)d_in[4];
    const float* Wo  = (const float*)d_in[5];
    const float* bo  = (const float*)d_in[6];
    // d_in[7] = time (unused: reweight always applies for time >= 0)

    float* out = (float*)d_out;                       // (B, N, 320)
    float* sim = out + (size_t)Bn * Nn * QD;          // (B, H, N, 77)

    float *qp = nullptr, *op = nullptr;
    cudaGetSymbolAddress((void**)&qp, g_q);
    cudaGetSymbolAddress((void**)&op, g_o);

    cudaFuncSetAttribute(attn_kernel, cudaFuncAttributeMaxDynamicSharedMemorySize,
                         ATTN_SMEM_B);

    // K & V projections (one launch)
    sgemm_kv<<<dim3((2 * ID) / 64, (KVROWS + 63) / 64), 256>>>(ctx, Wk, Wv);

    // Q projection (tf32 tensor cores)
    gemm_tf32<false><<<dim3(320 / 64, MROWS / 128), 256>>>(x, Wq, nullptr, qp);

    // fused attention (tensor-core QK^T and PV, FFMA softmax)
    attn_kernel<<<dim3(Nn / 128, Bn * Hh), 256, ATTN_SMEM_B>>>(qp, sim, op);

    // output projection + bias (tf32 tensor cores)
    gemm_tf32<true><<<dim3(320 / 64, MROWS / 128), 256>>>(op, Wo, bo, out);
}

// round 7
// speedup vs baseline: 2.1815x; 1.2744x over previous
#include <cuda_runtime.h>
#include <cstdint>
#include <cstddef>

// ---------------- problem constants ----------------
constexpr int Bn  = 6;
constexpr int Nn  = 4096;
constexpr int QD  = 320;
constexpr int CN  = 77;
constexpr int CD  = 768;
constexpr int Hh  = 8;
constexpr int DH  = 40;
constexpr int ID  = Hh * DH;          // 320 inner dim
constexpr float SCALE = 0.15811388300841897f; // 40^-0.5

constexpr int MROWS = Bn * Nn;        // 24576
constexpr int KVROWS = Bn * CN;       // 462

// single extern shared symbol (attn only)
extern __shared__ char smem_raw[];

// ---------------- scratch (static device memory; no allocs allowed) ------
__device__ float g_q [ (size_t)MROWS * ID ];     // q projection, (B*N, 320)
__device__ float g_o [ (size_t)MROWS * ID ];     // attn@v merged heads, (B*N, 320)
__device__ float g_kv[ (size_t)KVROWS * 2 * ID ];// (B*CN, 640): [0,320)=K, [320,640)=V
__device__ float g_wt[ 2 * 320 * 320 ];          // Wq^T, Wo^T (tf32-rounded, N-major)

// ---------------- helpers ----------------
__device__ __forceinline__ uint32_t f2tf32(float f) {
    uint32_t r;
    asm("cvt.rna.tf32.f32 %0, %1;" : "=r"(r) : "f"(f));
    return r;
}
__device__ __forceinline__ uint4 tf32x4(float4 v) {
    uint4 r;
    r.x = f2tf32(v.x); r.y = f2tf32(v.y);
    r.z = f2tf32(v.z); r.w = f2tf32(v.w);
    return r;
}
// FFMA-only exp (x <= 0 expected; relative error ~2.5e-6)
__device__ __forceinline__ float fast_exp(float x) {
    x = fmaxf(x, -60.f);
    float y = x * 1.4426950408889634f;        // x * log2(e)
    int   n = __float2int_rn(y);
    float f = y - (float)n;
    float t = f * 0.6931471805599453f;        // f * ln2
    float p = 8.3333333333e-3f;
    p = fmaf(p, t, 4.1666666667e-2f);
    p = fmaf(p, t, 1.6666666667e-1f);
    p = fmaf(p, t, 0.5f);
    p = fmaf(p, t, 1.0f);
    p = fmaf(p, t, 1.0f);
    return __int_as_float(__float_as_int(p) + (n << 23));
}

#define MMA_TF32(acc, a0, a1, a2, a3, b0, b1)                                   \
    asm volatile(                                                               \
        "mma.sync.aligned.m16n8k8.row.col.f32.tf32.tf32.f32 "                   \
        "{%0,%1,%2,%3}, {%4,%5,%6,%7}, {%8,%9}, {%0,%1,%2,%3};\n"               \
        : "+f"(acc[0]), "+f"(acc[1]), "+f"(acc[2]), "+f"(acc[3])                \
        : "r"(a0), "r"(a1), "r"(a2), "r"(a3), "r"(b0), "r"(b1))

// =====================================================================
// W transpose + tf32 round: g_wt[sel][n][k] = tf32(W[k][n]), 320x320
// =====================================================================
__global__ void transpose_w(const float* __restrict__ Wq, const float* __restrict__ Wo)
{
    __shared__ float tile[32][33];
    const float* W = (blockIdx.z == 0) ? Wq : Wo;
    float* Wt = g_wt + (size_t)blockIdx.z * 320 * 320;
    const int kBase = blockIdx.y * 32;   // source row (k)
    const int nBase = blockIdx.x * 32;   // source col (n)
    const int tx = threadIdx.x, ty = threadIdx.y;  // (32, 8)
    #pragma unroll
    for (int i = 0; i < 4; i++)
        tile[ty + 8 * i][tx] = W[(size_t)(kBase + ty + 8 * i) * 320 + nBase + tx];
    __syncthreads();
    #pragma unroll
    for (int i = 0; i < 4; i++) {
        uint32_t v = f2tf32(tile[tx][ty + 8 * i]);
        Wt[(size_t)(nBase + ty + 8 * i) * 320 + kBase + tx] = __uint_as_float(v);
    }
}

// =====================================================================
// TF32 tensor-core GEMM v2: C(24576x320) = A @ W (+bias)
// BM=128, BN=64, BK=32, 128 threads (4 warps, 2M x 2N, warp tile 64x32).
// A smem [128][36] row-major-k; B smem [64][36] n-major-k (from Wt).
// Both fragment patterns bank = (4g + t) mod 32 -> conflict-free.
// LDS/MMA = 1.5 (was 2.0 with 2-way conflicts on B).
// =====================================================================
template<bool BIAS>
__global__ void __launch_bounds__(128) gemm_tf32(
    const float* __restrict__ A,      // (24576, 320)
    const float* __restrict__ Wt,     // (320, 320) N-major, tf32-rounded
    const float* __restrict__ bias,   // (320) or null
    float* __restrict__ C)            // (24576, 320)
{
    constexpr int Nc = 320, K = 320;
    constexpr int BK = 32;
    constexpr int STRIDE = 36;    // 36 % 32 == 4 -> conflict-free fragments

    __shared__ uint32_t As[128][STRIDE];   // 18,432 B
    __shared__ uint32_t Bs[64][STRIDE];    //  9,216 B

    const int tid  = threadIdx.x;
    const int lane = tid & 31;
    const int wid  = tid >> 5;
    const int warpM = wid & 1;        // 0..1 -> 64-row slice
    const int warpN = wid >> 1;       // 0..1 -> 32-col slice
    const int g = lane >> 2;          // 0..7
    const int t = lane & 3;           // 0..3

    const int rowBase = blockIdx.y * 128;
    const int colBase = blockIdx.x * 64;

    // staging maps (128 threads; 8 uint4/row for 32-float rows)
    const int sr = tid >> 3;          // 0..15 (base row, step 16)
    const int sc4 = (tid & 7) * 4;    // float col 0,4,...,28

    const float* aPtr = A  + (size_t)(rowBase + sr) * K + sc4;
    const float* bPtr = Wt + (size_t)(colBase + sr) * K + sc4;

    float4 aR[8], bR[4];
    #pragma unroll
    for (int i = 0; i < 8; i++) aR[i] = *(const float4*)(aPtr + (size_t)(16 * i) * K);
    #pragma unroll
    for (int i = 0; i < 4; i++) bR[i] = *(const float4*)(bPtr + (size_t)(16 * i) * K);

    float acc[4][4][4];
    #pragma unroll
    for (int mt = 0; mt < 4; mt++)
        #pragma unroll
        for (int nt = 0; nt < 4; nt++)
            #pragma unroll
            for (int r = 0; r < 4; r++) acc[mt][nt][r] = 0.f;

    for (int k0 = 0; k0 < K; k0 += BK) {
        // store staged tiles (A cvt to tf32; B pre-rounded)
        #pragma unroll
        for (int i = 0; i < 8; i++)
            *(uint4*)&As[sr + 16 * i][sc4] = tf32x4(aR[i]);
        #pragma unroll
        for (int i = 0; i < 4; i++) {
            float4 v = bR[i];
            uint4 u;
            u.x = __float_as_uint(v.x); u.y = __float_as_uint(v.y);
            u.z = __float_as_uint(v.z); u.w = __float_as_uint(v.w);
            *(uint4*)&Bs[sr + 16 * i][sc4] = u;
        }
        __syncthreads();

        // prefetch next stage
        if (k0 + BK < K) {
            #pragma unroll
            for (int i = 0; i < 8; i++)
                aR[i] = *(const float4*)(aPtr + (size_t)(16 * i) * K + k0 + BK);
            #pragma unroll
            for (int i = 0; i < 4; i++)
                bR[i] = *(const float4*)(bPtr + (size_t)(16 * i) * K + k0 + BK);
        }

        #pragma unroll
        for (int kk = 0; kk < 4; kk++) {
            const int kc = kk * 8;
            uint32_t a[4][4], b[4][2];
            #pragma unroll
            for (int mt = 0; mt < 4; mt++) {
                const int r0 = warpM * 64 + mt * 16 + g;
                a[mt][0] = As[r0    ][kc + t    ];
                a[mt][1] = As[r0 + 8][kc + t    ];
                a[mt][2] = As[r0    ][kc + t + 4];
                a[mt][3] = As[r0 + 8][kc + t + 4];
            }
            #pragma unroll
            for (int nt = 0; nt < 4; nt++) {
                const int n0 = warpN * 32 + nt * 8 + g;
                b[nt][0] = Bs[n0][kc + t    ];
                b[nt][1] = Bs[n0][kc + t + 4];
            }
            #pragma unroll
            for (int mt = 0; mt < 4; mt++)
                #pragma unroll
                for (int nt = 0; nt < 4; nt++)
                    MMA_TF32(acc[mt][nt], a[mt][0], a[mt][1], a[mt][2], a[mt][3],
                             b[nt][0], b[nt][1]);
        }
        __syncthreads();
    }

    // epilogue
    #pragma unroll
    for (int mt = 0; mt < 4; mt++) {
        const int row = rowBase + warpM * 64 + mt * 16 + g;
        #pragma unroll
        for (int nt = 0; nt < 4; nt++) {
            const int col = colBase + warpN * 32 + nt * 8 + 2 * t;
            float b0 = 0.f, b1 = 0.f;
            if (BIAS) { b0 = bias[col]; b1 = bias[col + 1]; }
            float2 lo, hi;
            lo.x = acc[mt][nt][0] + b0; lo.y = acc[mt][nt][1] + b1;
            hi.x = acc[mt][nt][2] + b0; hi.y = acc[mt][nt][3] + b1;
            *(float2*)&C[(size_t)row * Nc + col]       = lo;
            *(float2*)&C[(size_t)(row + 8) * Nc + col] = hi;
        }
    }
}

// =====================================================================
// K/V projection in ONE launch (fp32 FFMA; tiny: 462x640x768)
// =====================================================================
__global__ void __launch_bounds__(256) sgemm_kv(
    const float* __restrict__ A,      // (462, 768)
    const float* __restrict__ Wk,     // (768, 320)
    const float* __restrict__ Wv)     // (768, 320)
{
    constexpr int M = KVROWS, K = CD, NW = ID, NC = 2 * ID;
    __shared__ float As[16][64 + 4];
    __shared__ float Bs[16][64];

    const int tid = threadIdx.x;
    const int colBase = blockIdx.x * 64;
    const int rowBase = blockIdx.y * 64;
    const float* Bm = (colBase < NW) ? Wk : Wv;
    const int cb = (colBase < NW) ? colBase : colBase - NW;

    const int tx = tid & 15, ty = tid >> 4;
    const int ar = tid >> 2;
    const int ac = (tid & 3) << 2;
    const int br = tid >> 4;
    const int bc = (tid & 15) << 2;

    float acc[4][4];
    #pragma unroll
    for (int i = 0; i < 4; i++)
        #pragma unroll
        for (int j = 0; j < 4; j++) acc[i][j] = 0.f;

    for (int k0 = 0; k0 < K; k0 += 16) {
        const int grow = rowBase + ar;
        float4 a = (grow < M) ? *(const float4*)&A[(size_t)grow * K + k0 + ac]
                              : make_float4(0.f, 0.f, 0.f, 0.f);
        float4 b = *(const float4*)&Bm[(size_t)(k0 + br) * NW + cb + bc];
        As[ac+0][ar] = a.x; As[ac+1][ar] = a.y; As[ac+2][ar] = a.z; As[ac+3][ar] = a.w;
        *(float4*)&Bs[br][bc] = b;
        __syncthreads();

        #pragma unroll
        for (int kk = 0; kk < 16; kk++) {
            float av[4], bv[4];
            #pragma unroll
            for (int i = 0; i < 4; i++) av[i] = As[kk][ty * 4 + i];
            #pragma unroll
            for (int j = 0; j < 4; j++) bv[j] = Bs[kk][tx * 4 + j];
            #pragma unroll
            for (int i = 0; i < 4; i++)
                #pragma unroll
                for (int j = 0; j < 4; j++) acc[i][j] += av[i] * bv[j];
        }
        __syncthreads();
    }

    #pragma unroll
    for (int i = 0; i < 4; i++) {
        const int r = rowBase + ty * 4 + i;
        if (r < M) {
            float4 v; v.x = acc[i][0]; v.y = acc[i][1]; v.z = acc[i][2]; v.w = acc[i][3];
            *(float4*)&g_kv[(size_t)r * NC + colBase + tx * 4] = v;
        }
    }
}

// =====================================================================
// Tensor-core fused attention (unchanged from R6 pass).
// =====================================================================
constexpr int SS_STRIDE = 84;
constexpr int ATTN_SMEM_B =
    (128 * DH + 80 * DH + 80 * DH + 128 * SS_STRIDE + 128) * 4;  // 89,600 B

__global__ void __launch_bounds__(256) attn_kernel(
    const float* __restrict__ q,    // (B*N, 320)
    float* __restrict__ sim,        // (B,H,N,77)
    float* __restrict__ o)          // (B*N, 320)
{
    float* Qs   = (float*)smem_raw;            // [128][40]
    float* Ks   = Qs + 128 * DH;               // [80][40]
    float* Vs   = Ks + 80 * DH;                // [80][40]
    float* Ss   = Vs + 80 * DH;                // [128][84]
    float* Sinv = Ss + 128 * SS_STRIDE;        // [128]

    const int bh = blockIdx.y;
    const int b = bh >> 3;
    const int h = bh & 7;
    const int tid  = threadIdx.x;
    const int lane = tid & 31;
    const int wid  = tid >> 5;
    const int g = lane >> 2;
    const int t = lane & 3;
    const int nBase = blockIdx.x * 128;

    {
        const float* qb = q + ((size_t)(b * Nn + nBase)) * ID + h * DH;
        #pragma unroll
        for (int i = 0; i < 5; i++) {
            const int idx = tid + 256 * i;
            const int r = idx / 10, c4 = (idx - r * 10) * 4;
            float4 v = *(const float4*)(qb + (size_t)r * ID + c4);
            *(uint4*)&Qs[r * DH + c4] = tf32x4(v);
        }
    }
    for (int idx = tid; idx < CN * 10; idx += 256) {
        const int r = idx / 10, c4 = (idx - r * 10) * 4;
        const float* base = g_kv + (size_t)(b * CN + r) * (2 * ID) + h * DH + c4;
        *(uint4*)&Ks[r * DH + c4] = tf32x4(*(const float4*)(base));
        *(uint4*)&Vs[r * DH + c4] = tf32x4(*(const float4*)(base + ID));
    }
    if (tid < 120) {
        Ks[CN * DH + tid] = 0.f;
        Vs[CN * DH + tid] = 0.f;
    }
    __syncthreads();

    {
        const int wm = wid & 3;
        const int wn = wid >> 2;
        float acc[2][5][4];
        #pragma unroll
        for (int m = 0; m < 2; m++)
            #pragma unroll
            for (int nt = 0; nt < 5; nt++)
                #pragma unroll
                for (int r = 0; r < 4; r++) acc[m][nt][r] = 0.f;

        #pragma unroll
        for (int ks = 0; ks < 5; ks++) {
            const int kc = ks * 8;
            uint32_t a[2][4], bfr[5][2];
            #pragma unroll
            for (int m = 0; m < 2; m++) {
                const int r0 = wm * 32 + m * 16 + g;
                a[m][0] = __float_as_uint(Qs[(r0    ) * DH + kc + t    ]);
                a[m][1] = __float_as_uint(Qs[(r0 + 8) * DH + kc + t    ]);
                a[m][2] = __float_as_uint(Qs[(r0    ) * DH + kc + t + 4]);
                a[m][3] = __float_as_uint(Qs[(r0 + 8) * DH + kc + t + 4]);
            }
            #pragma unroll
            for (int nt = 0; nt < 5; nt++) {
                const int n0 = wn * 40 + nt * 8 + g;
                bfr[nt][0] = __float_as_uint(Ks[n0 * DH + kc + t    ]);
                bfr[nt][1] = __float_as_uint(Ks[n0 * DH + kc + t + 4]);
            }
            #pragma unroll
            for (int m = 0; m < 2; m++)
                #pragma unroll
                for (int nt = 0; nt < 5; nt++)
                    MMA_TF32(acc[m][nt], a[m][0], a[m][1], a[m][2], a[m][3],
                             bfr[nt][0], bfr[nt][1]);
        }
        #pragma unroll
        for (int m = 0; m < 2; m++) {
            const int r0 = wm * 32 + m * 16 + g;
            #pragma unroll
            for (int nt = 0; nt < 5; nt++) {
                const int c = wn * 40 + nt * 8 + 2 * t;
                float2 lo, hi;
                lo.x = acc[m][nt][0] * SCALE; lo.y = acc[m][nt][1] * SCALE;
                hi.x = acc[m][nt][2] * SCALE; hi.y = acc[m][nt][3] * SCALE;
                *(float2*)&Ss[(r0    ) * SS_STRIDE + c] = lo;
                *(float2*)&Ss[(r0 + 8) * SS_STRIDE + c] = hi;
            }
        }
    }
    __syncthreads();

    {
        #pragma unroll
        for (int rr = 0; rr < 16; rr++) {
            const int r = wid * 16 + rr;
            float* dst = sim + ((size_t)bh * Nn + nBase + r) * CN;
            const float* src = Ss + r * SS_STRIDE;
            dst[lane]      = src[lane];
            dst[lane + 32] = src[lane + 32];
            if (lane < CN - 64) dst[lane + 64] = src[lane + 64];
        }
    }
    __syncthreads();

    {
        const int r = tid >> 1;
        const int half = tid & 1;
        float* srow = Ss + r * SS_STRIDE;
        const int j0 = half ? 40 : 0;
        const int j1 = half ? CN : 40;

        float m = -1e30f;
        for (int j = j0; j < j1; j++) m = fmaxf(m, srow[j]);
        m = fmaxf(m, __shfl_xor_sync(0xFFFFFFFF, m, 1));

        float sum = 0.f;
        for (int j = j0; j < j1; j++) {
            float e = fast_exp(srow[j] - m);
            sum += e;
            srow[j] = e;
        }
        sum += __shfl_xor_sync(0xFFFFFFFF, sum, 1);

        if (!half) {
            Sinv[r] = 1.f / sum;
            float w = 1.f;
            if (b == 3) w = -2.f; else if (b == 5) w = 5.f;
            srow[2] *= w;
        }
    }
    __syncthreads();
    for (int i = tid; i < 128 * CN; i += 256) {
        const int r = i / CN, c = i - r * CN;
        float* p = &Ss[r * SS_STRIDE + c];
        *p = __uint_as_float(f2tf32(*p));
    }
    __syncthreads();

    {
        const int m0 = wid * 16;
        float acc[5][4];
        #pragma unroll
        for (int nt = 0; nt < 5; nt++)
            #pragma unroll
            for (int r = 0; r < 4; r++) acc[nt][r] = 0.f;

        #pragma unroll
        for (int ks = 0; ks < 10; ks++) {
            const int kc = ks * 8;
            uint32_t a[4], bfr[5][2];
            a[0] = __float_as_uint(Ss[(m0 + g    ) * SS_STRIDE + kc + t    ]);
            a[1] = __float_as_uint(Ss[(m0 + g + 8) * SS_STRIDE + kc + t    ]);
            a[2] = __float_as_uint(Ss[(m0 + g    ) * SS_STRIDE + kc + t + 4]);
            a[3] = __float_as_uint(Ss[(m0 + g + 8) * SS_STRIDE + kc + t + 4]);
            #pragma unroll
            for (int nt = 0; nt < 5; nt++) {
                const int n0 = nt * 8 + g;
                bfr[nt][0] = __float_as_uint(Vs[(kc + t    ) * DH + n0]);
                bfr[nt][1] = __float_as_uint(Vs[(kc + t + 4) * DH + n0]);
            }
            #pragma unroll
            for (int nt = 0; nt < 5; nt++)
                MMA_TF32(acc[nt], a[0], a[1], a[2], a[3], bfr[nt][0], bfr[nt][1]);
        }

        const int r0 = m0 + g;
        const float inv0 = Sinv[r0];
        const float inv1 = Sinv[r0 + 8];
        float* o0 = o + ((size_t)(b * Nn + nBase + r0    )) * ID + h * DH;
        float* o1 = o + ((size_t)(b * Nn + nBase + r0 + 8)) * ID + h * DH;
        #pragma unroll
        for (int nt = 0; nt < 5; nt++) {
            const int c = nt * 8 + 2 * t;
            float2 lo, hi;
            lo.x = acc[nt][0] * inv0; lo.y = acc[nt][1] * inv0;
            hi.x = acc[nt][2] * inv1; hi.y = acc[nt][3] * inv1;
            *(float2*)(o0 + c) = lo;
            *(float2*)(o1 + c) = hi;
        }
    }
}

// =====================================================================
// launch
// =====================================================================
extern "C" void kernel_launch(void* const* d_in, const int* in_sizes, int n_in,
                              void* d_out, int out_size)
{
    const float* x   = (const float*)d_in[0];
    const float* ctx = (const float*)d_in[1];
    const float* Wq  = (const float*)d_in[2];
    const float* Wk  = (const float*)d_in[3];
    const float* Wv  = (const float*)d_in[4];
    const float* Wo  = (const float*)d_in[5];
    const float* bo  = (const float*)d_in[6];
    // d_in[7] = time (unused: reweight always applies for time >= 0)

    float* out = (float*)d_out;                       // (B, N, 320)
    float* sim = out + (size_t)Bn * Nn * QD;          // (B, H, N, 77)

    float *qp = nullptr, *op = nullptr, *wt = nullptr;
    cudaGetSymbolAddress((void**)&qp, g_q);
    cudaGetSymbolAddress((void**)&op, g_o);
    cudaGetSymbolAddress((void**)&wt, g_wt);

    cudaFuncSetAttribute(attn_kernel, cudaFuncAttributeMaxDynamicSharedMemorySize,
                         ATTN_SMEM_B);

    // transpose + tf32-round Wq, Wo (independent of everything else)
    transpose_w<<<dim3(10, 10, 2), dim3(32, 8)>>>(Wq, Wo);

    // K & V projections (one launch)
    sgemm_kv<<<dim3((2 * ID) / 64, (KVROWS + 63) / 64), 256>>>(ctx, Wk, Wv);

    // Q projection (tf32 tensor cores, conflict-free B)
    gemm_tf32<false><<<dim3(320 / 64, MROWS / 128), 128>>>(x, wt, nullptr, qp);

    // fused attention (tensor-core QK^T and PV, FFMA softmax)
    attn_kernel<<<dim3(Nn / 128, Bn * Hh), 256, ATTN_SMEM_B>>>(qp, sim, op);

    // output projection + bias (tf32 tensor cores, conflict-free B)
    gemm_tf32<true><<<dim3(320 / 64, MROWS / 128), 128>>>(op, wt + 320 * 320, bo, out);
}

// round 9
// speedup vs baseline: 2.2049x; 1.0107x over previous
#include <cuda_runtime.h>
#include <cstdint>
#include <cstddef>

// ---------------- problem constants ----------------
constexpr int Bn  = 6;
constexpr int Nn  = 4096;
constexpr int QD  = 320;
constexpr int CN  = 77;
constexpr int CD  = 768;
constexpr int Hh  = 8;
constexpr int DH  = 40;
constexpr int ID  = Hh * DH;          // 320 inner dim
constexpr float SCALE = 0.15811388300841897f; // 40^-0.5

constexpr int MROWS = Bn * Nn;        // 24576
constexpr int KVROWS = Bn * CN;       // 462

// single extern shared symbol (attn only)
extern __shared__ char smem_raw[];

// ---------------- scratch (static device memory; no allocs allowed) ------
__device__ float g_q [ (size_t)MROWS * ID ];     // q projection, (B*N, 320)
__device__ float g_o [ (size_t)MROWS * ID ];     // attn@v merged heads, (B*N, 320)
__device__ float g_kv[ (size_t)KVROWS * 2 * ID ];// (B*CN, 640): [0,320)=K, [320,640)=V
__device__ float g_wt[ 2 * 320 * 320 ];          // Wq^T, Wo^T (tf32-rounded, N-major)

// ---------------- helpers ----------------
__device__ __forceinline__ uint32_t f2tf32(float f) {
    uint32_t r;
    asm("cvt.rna.tf32.f32 %0, %1;" : "=r"(r) : "f"(f));
    return r;
}
__device__ __forceinline__ uint4 tf32x4(float4 v) {
    uint4 r;
    r.x = f2tf32(v.x); r.y = f2tf32(v.y);
    r.z = f2tf32(v.z); r.w = f2tf32(v.w);
    return r;
}
// FFMA-only exp (relative error ~2.5e-6)
__device__ __forceinline__ float fast_exp(float x) {
    x = fmaxf(x, -60.f);
    float y = x * 1.4426950408889634f;
    int   n = __float2int_rn(y);
    float f = y - (float)n;
    float t = f * 0.6931471805599453f;
    float p = 8.3333333333e-3f;
    p = fmaf(p, t, 4.1666666667e-2f);
    p = fmaf(p, t, 1.6666666667e-1f);
    p = fmaf(p, t, 0.5f);
    p = fmaf(p, t, 1.0f);
    p = fmaf(p, t, 1.0f);
    return __int_as_float(__float_as_int(p) + (n << 23));
}

#define MMA_TF32(acc, a0, a1, a2, a3, b0, b1)                                   \
    asm volatile(                                                               \
        "mma.sync.aligned.m16n8k8.row.col.f32.tf32.tf32.f32 "                   \
        "{%0,%1,%2,%3}, {%4,%5,%6,%7}, {%8,%9}, {%0,%1,%2,%3};\n"               \
        : "+f"(acc[0]), "+f"(acc[1]), "+f"(acc[2]), "+f"(acc[3])                \
        : "r"(a0), "r"(a1), "r"(a2), "r"(a3), "r"(b0), "r"(b1))

// =====================================================================
// W transpose + tf32 round: g_wt[sel][n][k] = tf32(W[k][n]), 320x320
// =====================================================================
__global__ void transpose_w(const float* __restrict__ Wq, const float* __restrict__ Wo)
{
    __shared__ float tile[32][33];
    const float* W = (blockIdx.z == 0) ? Wq : Wo;
    float* Wt = g_wt + (size_t)blockIdx.z * 320 * 320;
    const int kBase = blockIdx.y * 32;
    const int nBase = blockIdx.x * 32;
    const int tx = threadIdx.x, ty = threadIdx.y;  // (32, 8)
    #pragma unroll
    for (int i = 0; i < 4; i++)
        tile[ty + 8 * i][tx] = W[(size_t)(kBase + ty + 8 * i) * 320 + nBase + tx];
    __syncthreads();
    #pragma unroll
    for (int i = 0; i < 4; i++) {
        uint32_t v = f2tf32(tile[tx][ty + 8 * i]);
        Wt[(size_t)(nBase + ty + 8 * i) * 320 + kBase + tx] = __uint_as_float(v);
    }
}

// =====================================================================
// TF32 tensor-core GEMM v2 (R7-proven): 128x64 tile, 128 thr, warp 64x32
// =====================================================================
template<bool BIAS>
__global__ void __launch_bounds__(128) gemm_tf32(
    const float* __restrict__ A,      // (24576, 320)
    const float* __restrict__ Wt,     // (320, 320) N-major, tf32-rounded
    const float* __restrict__ bias,   // (320) or null
    float* __restrict__ C)            // (24576, 320)
{
    constexpr int Nc = 320, K = 320;
    constexpr int BK = 32;
    constexpr int STRIDE = 36;

    __shared__ uint32_t As[128][STRIDE];
    __shared__ uint32_t Bs[64][STRIDE];

    const int tid  = threadIdx.x;
    const int lane = tid & 31;
    const int wid  = tid >> 5;
    const int warpM = wid & 1;
    const int warpN = wid >> 1;
    const int g = lane >> 2;
    const int t = lane & 3;

    const int rowBase = blockIdx.y * 128;
    const int colBase = blockIdx.x * 64;

    const int sr = tid >> 3;
    const int sc4 = (tid & 7) * 4;

    const float* aPtr = A  + (size_t)(rowBase + sr) * K + sc4;
    const float* bPtr = Wt + (size_t)(colBase + sr) * K + sc4;

    float4 aR[8], bR[4];
    #pragma unroll
    for (int i = 0; i < 8; i++) aR[i] = *(const float4*)(aPtr + (size_t)(16 * i) * K);
    #pragma unroll
    for (int i = 0; i < 4; i++) bR[i] = *(const float4*)(bPtr + (size_t)(16 * i) * K);

    float acc[4][4][4];
    #pragma unroll
    for (int mt = 0; mt < 4; mt++)
        #pragma unroll
        for (int nt = 0; nt < 4; nt++)
            #pragma unroll
            for (int r = 0; r < 4; r++) acc[mt][nt][r] = 0.f;

    for (int k0 = 0; k0 < K; k0 += BK) {
        #pragma unroll
        for (int i = 0; i < 8; i++)
            *(uint4*)&As[sr + 16 * i][sc4] = tf32x4(aR[i]);
        #pragma unroll
        for (int i = 0; i < 4; i++) {
            float4 v = bR[i];
            uint4 u;
            u.x = __float_as_uint(v.x); u.y = __float_as_uint(v.y);
            u.z = __float_as_uint(v.z); u.w = __float_as_uint(v.w);
            *(uint4*)&Bs[sr + 16 * i][sc4] = u;
        }
        __syncthreads();

        if (k0 + BK < K) {
            #pragma unroll
            for (int i = 0; i < 8; i++)
                aR[i] = *(const float4*)(aPtr + (size_t)(16 * i) * K + k0 + BK);
            #pragma unroll
            for (int i = 0; i < 4; i++)
                bR[i] = *(const float4*)(bPtr + (size_t)(16 * i) * K + k0 + BK);
        }

        #pragma unroll
        for (int kk = 0; kk < 4; kk++) {
            const int kc = kk * 8;
            uint32_t a[4][4], b[4][2];
            #pragma unroll
            for (int mt = 0; mt < 4; mt++) {
                const int r0 = warpM * 64 + mt * 16 + g;
                a[mt][0] = As[r0    ][kc + t    ];
                a[mt][1] = As[r0 + 8][kc + t    ];
                a[mt][2] = As[r0    ][kc + t + 4];
                a[mt][3] = As[r0 + 8][kc + t + 4];
            }
            #pragma unroll
            for (int nt = 0; nt < 4; nt++) {
                const int n0 = warpN * 32 + nt * 8 + g;
                b[nt][0] = Bs[n0][kc + t    ];
                b[nt][1] = Bs[n0][kc + t + 4];
            }
            #pragma unroll
            for (int mt = 0; mt < 4; mt++)
                #pragma unroll
                for (int nt = 0; nt < 4; nt++)
                    MMA_TF32(acc[mt][nt], a[mt][0], a[mt][1], a[mt][2], a[mt][3],
                             b[nt][0], b[nt][1]);
        }
        __syncthreads();
    }

    #pragma unroll
    for (int mt = 0; mt < 4; mt++) {
        const int row = rowBase + warpM * 64 + mt * 16 + g;
        #pragma unroll
        for (int nt = 0; nt < 4; nt++) {
            const int col = colBase + warpN * 32 + nt * 8 + 2 * t;
            float b0 = 0.f, b1 = 0.f;
            if (BIAS) { b0 = bias[col]; b1 = bias[col + 1]; }
            float2 lo, hi;
            lo.x = acc[mt][nt][0] + b0; lo.y = acc[mt][nt][1] + b1;
            hi.x = acc[mt][nt][2] + b0; hi.y = acc[mt][nt][3] + b1;
            *(float2*)&C[(size_t)row * Nc + col]       = lo;
            *(float2*)&C[(size_t)(row + 8) * Nc + col] = hi;
        }
    }
}

// =====================================================================
// K/V projection in ONE launch (fp32 FFMA; tiny: 462x640x768)
// =====================================================================
__global__ void __launch_bounds__(256) sgemm_kv(
    const float* __restrict__ A,
    const float* __restrict__ Wk,
    const float* __restrict__ Wv)
{
    constexpr int M = KVROWS, K = CD, NW = ID, NC = 2 * ID;
    __shared__ float As[16][64 + 4];
    __shared__ float Bs[16][64];

    const int tid = threadIdx.x;
    const int colBase = blockIdx.x * 64;
    const int rowBase = blockIdx.y * 64;
    const float* Bm = (colBase < NW) ? Wk : Wv;
    const int cb = (colBase < NW) ? colBase : colBase - NW;

    const int tx = tid & 15, ty = tid >> 4;
    const int ar = tid >> 2;
    const int ac = (tid & 3) << 2;
    const int br = tid >> 4;
    const int bc = (tid & 15) << 2;

    float acc[4][4];
    #pragma unroll
    for (int i = 0; i < 4; i++)
        #pragma unroll
        for (int j = 0; j < 4; j++) acc[i][j] = 0.f;

    for (int k0 = 0; k0 < K; k0 += 16) {
        const int grow = rowBase + ar;
        float4 a = (grow < M) ? *(const float4*)&A[(size_t)grow * K + k0 + ac]
                              : make_float4(0.f, 0.f, 0.f, 0.f);
        float4 b = *(const float4*)&Bm[(size_t)(k0 + br) * NW + cb + bc];
        As[ac+0][ar] = a.x; As[ac+1][ar] = a.y; As[ac+2][ar] = a.z; As[ac+3][ar] = a.w;
        *(float4*)&Bs[br][bc] = b;
        __syncthreads();

        #pragma unroll
        for (int kk = 0; kk < 16; kk++) {
            float av[4], bv[4];
            #pragma unroll
            for (int i = 0; i < 4; i++) av[i] = As[kk][ty * 4 + i];
            #pragma unroll
            for (int j = 0; j < 4; j++) bv[j] = Bs[kk][tx * 4 + j];
            #pragma unroll
            for (int i = 0; i < 4; i++)
                #pragma unroll
                for (int j = 0; j < 4; j++) acc[i][j] += av[i] * bv[j];
        }
        __syncthreads();
    }

    #pragma unroll
    for (int i = 0; i < 4; i++) {
        const int r = rowBase + ty * 4 + i;
        if (r < M) {
            float4 v; v.x = acc[i][0]; v.y = acc[i][1]; v.z = acc[i][2]; v.w = acc[i][3];
            *(float4*)&g_kv[(size_t)r * NC + colBase + tx * 4] = v;
        }
    }
}

// =====================================================================
// Attention v3.1: register softmax; sim written with scalar STG.32
// (row stride 77 floats is odd -> float2 stores would be misaligned).
// =====================================================================
constexpr int SS_STRIDE = 84;
constexpr int ATTN_SMEM_B =
    (128 * DH + 80 * DH + 80 * DH + 128 * SS_STRIDE) * 4;  // 89,088 B

__global__ void __launch_bounds__(256) attn_kernel(
    const float* __restrict__ q,    // (B*N, 320)
    float* __restrict__ sim,        // (B,H,N,77)
    float* __restrict__ o)          // (B*N, 320)
{
    float* Qs = (float*)smem_raw;              // [128][40]
    float* Ks = Qs + 128 * DH;                 // [80][40]
    float* Vs = Ks + 80 * DH;                  // [80][40]
    float* Ss = Vs + 80 * DH;                  // [128][84]

    const int bh = blockIdx.y;
    const int b = bh >> 3;
    const int h = bh & 7;
    const int tid  = threadIdx.x;
    const int lane = tid & 31;
    const int wid  = tid >> 5;
    const int g = lane >> 2;
    const int t = lane & 3;
    const int nBase = blockIdx.x * 128;
    const int m0 = wid * 16;

    // ---- stage Q (tf32), K/V (tf32, rows 77..79 zeroed) ----
    {
        const float* qb = q + ((size_t)(b * Nn + nBase)) * ID + h * DH;
        #pragma unroll
        for (int i = 0; i < 5; i++) {
            const int idx = tid + 256 * i;
            const int r = idx / 10, c4 = (idx - r * 10) * 4;
            float4 v = *(const float4*)(qb + (size_t)r * ID + c4);
            *(uint4*)&Qs[r * DH + c4] = tf32x4(v);
        }
    }
    for (int idx = tid; idx < CN * 10; idx += 256) {
        const int r = idx / 10, c4 = (idx - r * 10) * 4;
        const float* base = g_kv + (size_t)(b * CN + r) * (2 * ID) + h * DH + c4;
        *(uint4*)&Ks[r * DH + c4] = tf32x4(*(const float4*)(base));
        *(uint4*)&Vs[r * DH + c4] = tf32x4(*(const float4*)(base + ID));
    }
    if (tid < 120) {
        Ks[CN * DH + tid] = 0.f;
        Vs[CN * DH + tid] = 0.f;
    }
    __syncthreads();

    // ---- QK^T: warp covers 16 rows x 80 cols ----
    float acc[10][4];
    #pragma unroll
    for (int nt = 0; nt < 10; nt++)
        #pragma unroll
        for (int r = 0; r < 4; r++) acc[nt][r] = 0.f;

    #pragma unroll
    for (int ks = 0; ks < 5; ks++) {
        const int kc = ks * 8;
        uint32_t a0, a1, a2, a3;
        a0 = __float_as_uint(Qs[(m0 + g    ) * DH + kc + t    ]);
        a1 = __float_as_uint(Qs[(m0 + g + 8) * DH + kc + t    ]);
        a2 = __float_as_uint(Qs[(m0 + g    ) * DH + kc + t + 4]);
        a3 = __float_as_uint(Qs[(m0 + g + 8) * DH + kc + t + 4]);
        #pragma unroll
        for (int nt = 0; nt < 10; nt++) {
            const int n0 = nt * 8 + g;
            uint32_t b0 = __float_as_uint(Ks[n0 * DH + kc + t    ]);
            uint32_t b1 = __float_as_uint(Ks[n0 * DH + kc + t + 4]);
            MMA_TF32(acc[nt], a0, a1, a2, a3, b0, b1);
        }
    }
    // scale
    #pragma unroll
    for (int nt = 0; nt < 10; nt++)
        #pragma unroll
        for (int r = 0; r < 4; r++) acc[nt][r] *= SCALE;

    // ---- sim write straight from registers (scalar stores: stride 77) ----
    {
        float* s0 = sim + ((size_t)bh * Nn + nBase + m0 + g) * CN;
        float* s1 = s0 + 8 * (size_t)CN;
        #pragma unroll
        for (int nt = 0; nt < 10; nt++) {
            const int c = nt * 8 + 2 * t;
            if (c < CN) {
                s0[c] = acc[nt][0];
                s1[c] = acc[nt][2];
            }
            if (c + 1 < CN) {
                s0[c + 1] = acc[nt][1];
                s1[c + 1] = acc[nt][3];
            }
        }
    }

    // ---- softmax in registers (rows g and g+8 of this warp tile) ----
    {
        const bool in0 = (t <= 2);   // nt==9 comp0 col = 72+2t < 77
        const bool in1 = (t <= 1);   // nt==9 comp1 col = 73+2t < 77
        float mx0 = -1e30f, mx1 = -1e30f;
        #pragma unroll
        for (int nt = 0; nt < 9; nt++) {
            mx0 = fmaxf(mx0, fmaxf(acc[nt][0], acc[nt][1]));
            mx1 = fmaxf(mx1, fmaxf(acc[nt][2], acc[nt][3]));
        }
        if (in0) { mx0 = fmaxf(mx0, acc[9][0]); mx1 = fmaxf(mx1, acc[9][2]); }
        if (in1) { mx0 = fmaxf(mx0, acc[9][1]); mx1 = fmaxf(mx1, acc[9][3]); }
        mx0 = fmaxf(mx0, __shfl_xor_sync(0xFFFFFFFF, mx0, 1));
        mx0 = fmaxf(mx0, __shfl_xor_sync(0xFFFFFFFF, mx0, 2));
        mx1 = fmaxf(mx1, __shfl_xor_sync(0xFFFFFFFF, mx1, 1));
        mx1 = fmaxf(mx1, __shfl_xor_sync(0xFFFFFFFF, mx1, 2));

        float s0 = 0.f, s1 = 0.f;
        #pragma unroll
        for (int nt = 0; nt < 10; nt++) {
            float e0 = fast_exp(acc[nt][0] - mx0);
            float e1 = fast_exp(acc[nt][1] - mx0);
            float e2 = fast_exp(acc[nt][2] - mx1);
            float e3 = fast_exp(acc[nt][3] - mx1);
            if (nt == 9) {
                if (!in0) { e0 = 0.f; e2 = 0.f; }
                if (!in1) { e1 = 0.f; e3 = 0.f; }
            }
            acc[nt][0] = e0; acc[nt][1] = e1;
            acc[nt][2] = e2; acc[nt][3] = e3;
            s0 += e0 + e1;
            s1 += e2 + e3;
        }
        s0 += __shfl_xor_sync(0xFFFFFFFF, s0, 1);
        s0 += __shfl_xor_sync(0xFFFFFFFF, s0, 2);
        s1 += __shfl_xor_sync(0xFFFFFFFF, s1, 1);
        s1 += __shfl_xor_sync(0xFFFFFFFF, s1, 2);
        const float inv0 = 1.f / s0;
        const float inv1 = 1.f / s1;

        // token-2 reweight: col 2 = nt0, comp0, t==1
        float w = 1.f;
        if (b == 3) w = -2.f; else if (b == 5) w = 5.f;
        if (t == 1) { acc[0][0] *= w; acc[0][2] *= w; }

        // store normalized, tf32-rounded P
        float* p0 = &Ss[(m0 + g    ) * SS_STRIDE + 2 * t];
        float* p1 = &Ss[(m0 + g + 8) * SS_STRIDE + 2 * t];
        #pragma unroll
        for (int nt = 0; nt < 10; nt++) {
            float2 lo, hi;
            lo.x = __uint_as_float(f2tf32(acc[nt][0] * inv0));
            lo.y = __uint_as_float(f2tf32(acc[nt][1] * inv0));
            hi.x = __uint_as_float(f2tf32(acc[nt][2] * inv1));
            hi.y = __uint_as_float(f2tf32(acc[nt][3] * inv1));
            *(float2*)(p0 + nt * 8) = lo;
            *(float2*)(p1 + nt * 8) = hi;
        }
    }
    __syncthreads();

    // ---- P V: warp w -> rows m0..m0+15; N=40 (5 n-tiles); K=80 ----
    {
        float oacc[5][4];
        #pragma unroll
        for (int nt = 0; nt < 5; nt++)
            #pragma unroll
            for (int r = 0; r < 4; r++) oacc[nt][r] = 0.f;

        #pragma unroll
        for (int ks = 0; ks < 10; ks++) {
            const int kc = ks * 8;
            uint32_t a0, a1, a2, a3;
            a0 = __float_as_uint(Ss[(m0 + g    ) * SS_STRIDE + kc + t    ]);
            a1 = __float_as_uint(Ss[(m0 + g + 8) * SS_STRIDE + kc + t    ]);
            a2 = __float_as_uint(Ss[(m0 + g    ) * SS_STRIDE + kc + t + 4]);
            a3 = __float_as_uint(Ss[(m0 + g + 8) * SS_STRIDE + kc + t + 4]);
            #pragma unroll
            for (int nt = 0; nt < 5; nt++) {
                const int n0 = nt * 8 + g;
                uint32_t b0 = __float_as_uint(Vs[(kc + t    ) * DH + n0]);
                uint32_t b1 = __float_as_uint(Vs[(kc + t + 4) * DH + n0]);
                MMA_TF32(oacc[nt], a0, a1, a2, a3, b0, b1);
            }
        }

        float* o0 = o + ((size_t)(b * Nn + nBase + m0 + g    )) * ID + h * DH;
        float* o1 = o + ((size_t)(b * Nn + nBase + m0 + g + 8)) * ID + h * DH;
        #pragma unroll
        for (int nt = 0; nt < 5; nt++) {
            const int c = nt * 8 + 2 * t;
            float2 lo, hi;
            lo.x = oacc[nt][0]; lo.y = oacc[nt][1];
            hi.x = oacc[nt][2]; hi.y = oacc[nt][3];
            *(float2*)(o0 + c) = lo;
            *(float2*)(o1 + c) = hi;
        }
    }
}

// =====================================================================
// launch
// =====================================================================
extern "C" void kernel_launch(void* const* d_in, const int* in_sizes, int n_in,
                              void* d_out, int out_size)
{
    const float* x   = (const float*)d_in[0];
    const float* ctx = (const float*)d_in[1];
    const float* Wq  = (const float*)d_in[2];
    const float* Wk  = (const float*)d_in[3];
    const float* Wv  = (const float*)d_in[4];
    const float* Wo  = (const float*)d_in[5];
    const float* bo  = (const float*)d_in[6];
    // d_in[7] = time (unused: reweight always applies for time >= 0)

    float* out = (float*)d_out;                       // (B, N, 320)
    float* sim = out + (size_t)Bn * Nn * QD;          // (B, H, N, 77)

    float *qp = nullptr, *op = nullptr, *wt = nullptr;
    cudaGetSymbolAddress((void**)&qp, g_q);
    cudaGetSymbolAddress((void**)&op, g_o);
    cudaGetSymbolAddress((void**)&wt, g_wt);

    cudaFuncSetAttribute(attn_kernel, cudaFuncAttributeMaxDynamicSharedMemorySize,
                         ATTN_SMEM_B);

    // transpose + tf32-round Wq, Wo
    transpose_w<<<dim3(10, 10, 2), dim3(32, 8)>>>(Wq, Wo);

    // K & V projections (one launch)
    sgemm_kv<<<dim3((2 * ID) / 64, (KVROWS + 63) / 64), 256>>>(ctx, Wk, Wv);

    // Q projection (tf32 tensor cores)
    gemm_tf32<false><<<dim3(320 / 64, MROWS / 128), 128>>>(x, wt, nullptr, qp);

    // fused attention (register softmax)
    attn_kernel<<<dim3(Nn / 128, Bn * Hh), 256, ATTN_SMEM_B>>>(qp, sim, op);

    // output projection + bias (tf32 tensor cores)
    gemm_tf32<true><<<dim3(320 / 64, MROWS / 128), 128>>>(op, wt + 320 * 320, bo, out);
}

// round 11
// speedup vs baseline: 2.4553x; 1.1136x over previous
#include <cuda_runtime.h>
#include <cuda_fp16.h>
#include <cstdint>
#include <cstddef>

// ---------------- problem constants ----------------
constexpr int Bn  = 6;
constexpr int Nn  = 4096;
constexpr int QD  = 320;
constexpr int CN  = 77;
constexpr int CD  = 768;
constexpr int Hh  = 8;
constexpr int DH  = 40;
constexpr int ID  = Hh * DH;          // 320 inner dim
constexpr float SCALE = 0.15811388300841897f; // 40^-0.5

constexpr int MROWS = Bn * Nn;        // 24576
constexpr int KVROWS = Bn * CN;       // 462

// single extern shared symbol (attn only)
extern __shared__ char smem_raw[];

// ---------------- scratch (static device memory; no allocs allowed) ------
__device__ float  g_q [ (size_t)MROWS * ID ];     // q projection, (B*N, 320)
__device__ float  g_o [ (size_t)MROWS * ID ];     // attn@v merged heads, (B*N, 320)
__device__ float  g_kv[ (size_t)KVROWS * 2 * ID ];// (B*CN, 640): [0,320)=K, [320,640)=V
__device__ __half g_wt[ 2 * 320 * 320 ];          // Wq^T, Wo^T (fp16, N-major)

// ---------------- helpers ----------------
__device__ __forceinline__ uint32_t smem_u32(const void* p) {
    uint32_t a;
    asm("{ .reg .u64 t; cvta.to.shared.u64 t, %1; cvt.u32.u64 %0, t; }" : "=r"(a) : "l"(p));
    return a;
}
__device__ __forceinline__ uint32_t f2tf32(float f) {
    uint32_t r;
    asm("cvt.rna.tf32.f32 %0, %1;" : "=r"(r) : "f"(f));
    return r;
}
__device__ __forceinline__ uint4 tf32x4(float4 v) {
    uint4 r;
    r.x = f2tf32(v.x); r.y = f2tf32(v.y);
    r.z = f2tf32(v.z); r.w = f2tf32(v.w);
    return r;
}
// FFMA-only exp (relative error ~2.5e-6)
__device__ __forceinline__ float fast_exp(float x) {
    x = fmaxf(x, -60.f);
    float y = x * 1.4426950408889634f;
    int   n = __float2int_rn(y);
    float f = y - (float)n;
    float t = f * 0.6931471805599453f;
    float p = 8.3333333333e-3f;
    p = fmaf(p, t, 4.1666666667e-2f);
    p = fmaf(p, t, 1.6666666667e-1f);
    p = fmaf(p, t, 0.5f);
    p = fmaf(p, t, 1.0f);
    p = fmaf(p, t, 1.0f);
    return __int_as_float(__float_as_int(p) + (n << 23));
}

#define MMA_TF32(acc, a0, a1, a2, a3, b0, b1)                                   \
    asm volatile(                                                               \
        "mma.sync.aligned.m16n8k8.row.col.f32.tf32.tf32.f32 "                   \
        "{%0,%1,%2,%3}, {%4,%5,%6,%7}, {%8,%9}, {%0,%1,%2,%3};\n"               \
        : "+f"(acc[0]), "+f"(acc[1]), "+f"(acc[2]), "+f"(acc[3])                \
        : "r"(a0), "r"(a1), "r"(a2), "r"(a3), "r"(b0), "r"(b1))

#define MMA_F16(acc, a0, a1, a2, a3, b0, b1)                                    \
    asm volatile(                                                               \
        "mma.sync.aligned.m16n8k16.row.col.f32.f16.f16.f32 "                    \
        "{%0,%1,%2,%3}, {%4,%5,%6,%7}, {%8,%9}, {%0,%1,%2,%3};\n"               \
        : "+f"(acc[0]), "+f"(acc[1]), "+f"(acc[2]), "+f"(acc[3])                \
        : "r"(a0), "r"(a1), "r"(a2), "r"(a3), "r"(b0), "r"(b1))

#define LDMATRIX_X4(r0, r1, r2, r3, addr)                                       \
    asm volatile("ldmatrix.sync.aligned.m8n8.x4.shared.b16 {%0,%1,%2,%3}, [%4];"\
        : "=r"(r0), "=r"(r1), "=r"(r2), "=r"(r3) : "r"(addr))

// =====================================================================
// W transpose + fp16 convert: g_wt[sel][n][k] = half(W[k][n]), 320x320
// =====================================================================
__global__ void transpose_w(const float* __restrict__ Wq, const float* __restrict__ Wo)
{
    __shared__ float tile[32][33];
    const float* W = (blockIdx.z == 0) ? Wq : Wo;
    __half* Wt = g_wt + (size_t)blockIdx.z * 320 * 320;
    const int kBase = blockIdx.y * 32;
    const int nBase = blockIdx.x * 32;
    const int tx = threadIdx.x, ty = threadIdx.y;  // (32, 8)
    #pragma unroll
    for (int i = 0; i < 4; i++)
        tile[ty + 8 * i][tx] = W[(size_t)(kBase + ty + 8 * i) * 320 + nBase + tx];
    __syncthreads();
    #pragma unroll
    for (int i = 0; i < 4; i++)
        Wt[(size_t)(nBase + ty + 8 * i) * 320 + kBase + tx] =
            __float2half_rn(tile[tx][ty + 8 * i]);
}

// =====================================================================
// FP16 tensor-core GEMM v3.1: C(24576x320) = A @ W (+bias), fp32 acc.
// BM=128, BN=64, BK=32, 128 threads (4 warps 2Mx2N, warp 64x32).
// ldmatrix.x4 fragments; smem stride 40 halves -> LDSM conflict-free.
// FIX vs v3: B staging now uint4 (8 halves) per thread -> full coverage.
// =====================================================================
template<bool BIAS>
__global__ void __launch_bounds__(128) gemm_h16(
    const float*  __restrict__ A,      // (24576, 320) fp32
    const __half* __restrict__ Wt,     // (320, 320) N-major fp16
    const float*  __restrict__ bias,   // (320) or null
    float* __restrict__ C)             // (24576, 320)
{
    constexpr int Nc = 320, K = 320;
    constexpr int BK = 32;
    constexpr int HS = 40;             // half stride (pad 32 -> 40)

    __shared__ __half Ah[128][HS];     // 10,240 B
    __shared__ __half Bh[64][HS];      //  5,120 B

    const int tid  = threadIdx.x;
    const int lane = tid & 31;
    const int wid  = tid >> 5;
    const int warpM = wid & 1;
    const int warpN = wid >> 1;
    const int g = lane >> 2;
    const int t = lane & 3;
    const int lrow = lane & 7;
    const int lgrp = lane >> 3;        // 0..3

    const int rowBase = blockIdx.y * 128;
    const int colBase = blockIdx.x * 64;

    // staging maps
    const int sr  = tid >> 3;          // 0..15, A rows step 16
    const int sc4 = (tid & 7) * 4;     // A float col (4 floats -> 4 halves)
    const int br  = tid >> 2;          // 0..31, B rows step 32
    const int bc  = (tid & 3) * 8;     // B half col (8 halves = uint4)

    const float*  aPtr = A  + (size_t)(rowBase + sr) * K + sc4;
    const __half* bPtr = Wt + (size_t)(colBase + br) * K + bc;

    float4 aR[8];
    uint4  bR[2];
    #pragma unroll
    for (int i = 0; i < 8; i++) aR[i] = *(const float4*)(aPtr + (size_t)(16 * i) * K);
    bR[0] = *(const uint4*)(bPtr);
    bR[1] = *(const uint4*)(bPtr + (size_t)32 * K);

    float acc[4][4][4];
    #pragma unroll
    for (int mt = 0; mt < 4; mt++)
        #pragma unroll
        for (int nt = 0; nt < 4; nt++)
            #pragma unroll
            for (int r = 0; r < 4; r++) acc[mt][nt][r] = 0.f;

    // ldmatrix lane address components
    const int a_row = (lgrp & 1) * 8 + lrow;     // + mt*16 + warpM*64
    const int a_col = (lgrp >> 1) * 8;           // + kc
    const int b_row = (lgrp >> 1) * 8 + lrow;    // + nb*16 + warpN*32
    const int b_col = (lgrp & 1) * 8;            // + kc

    for (int k0 = 0; k0 < K; k0 += BK) {
        // store staged tiles (A fp32 -> fp16; B already fp16)
        #pragma unroll
        for (int i = 0; i < 8; i++) {
            float4 v = aR[i];
            __half2 h0 = __floats2half2_rn(v.x, v.y);
            __half2 h1 = __floats2half2_rn(v.z, v.w);
            uint2 u;
            u.x = *(const uint32_t*)&h0;
            u.y = *(const uint32_t*)&h1;
            *(uint2*)&Ah[sr + 16 * i][sc4] = u;
        }
        *(uint4*)&Bh[br][bc]      = bR[0];
        *(uint4*)&Bh[br + 32][bc] = bR[1];
        __syncthreads();

        // prefetch next stage
        if (k0 + BK < K) {
            #pragma unroll
            for (int i = 0; i < 8; i++)
                aR[i] = *(const float4*)(aPtr + (size_t)(16 * i) * K + k0 + BK);
            bR[0] = *(const uint4*)(bPtr + k0 + BK);
            bR[1] = *(const uint4*)(bPtr + (size_t)32 * K + k0 + BK);
        }

        #pragma unroll
        for (int kk = 0; kk < 2; kk++) {
            const int kc = kk * 16;
            uint32_t afr[4][4], bfr[4][2];
            #pragma unroll
            for (int mt = 0; mt < 4; mt++) {
                uint32_t addr = smem_u32(&Ah[warpM * 64 + mt * 16 + a_row][kc + a_col]);
                LDMATRIX_X4(afr[mt][0], afr[mt][1], afr[mt][2], afr[mt][3], addr);
            }
            #pragma unroll
            for (int nb = 0; nb < 2; nb++) {
                uint32_t addr = smem_u32(&Bh[warpN * 32 + nb * 16 + b_row][kc + b_col]);
                LDMATRIX_X4(bfr[2 * nb][0], bfr[2 * nb][1],
                            bfr[2 * nb + 1][0], bfr[2 * nb + 1][1], addr);
            }
            #pragma unroll
            for (int mt = 0; mt < 4; mt++)
                #pragma unroll
                for (int nt = 0; nt < 4; nt++)
                    MMA_F16(acc[mt][nt], afr[mt][0], afr[mt][1], afr[mt][2], afr[mt][3],
                            bfr[nt][0], bfr[nt][1]);
        }
        __syncthreads();
    }

    // epilogue
    #pragma unroll
    for (int mt = 0; mt < 4; mt++) {
        const int row = rowBase + warpM * 64 + mt * 16 + g;
        #pragma unroll
        for (int nt = 0; nt < 4; nt++) {
            const int col = colBase + warpN * 32 + nt * 8 + 2 * t;
            float b0 = 0.f, b1 = 0.f;
            if (BIAS) { b0 = bias[col]; b1 = bias[col + 1]; }
            float2 lo, hi;
            lo.x = acc[mt][nt][0] + b0; lo.y = acc[mt][nt][1] + b1;
            hi.x = acc[mt][nt][2] + b0; hi.y = acc[mt][nt][3] + b1;
            *(float2*)&C[(size_t)row * Nc + col]       = lo;
            *(float2*)&C[(size_t)(row + 8) * Nc + col] = hi;
        }
    }
}

// =====================================================================
// K/V projection in ONE launch (fp32 FFMA; tiny: 462x640x768)
// =====================================================================
__global__ void __launch_bounds__(256) sgemm_kv(
    const float* __restrict__ A,
    const float* __restrict__ Wk,
    const float* __restrict__ Wv)
{
    constexpr int M = KVROWS, K = CD, NW = ID, NC = 2 * ID;
    __shared__ float As[16][64 + 4];
    __shared__ float Bs[16][64];

    const int tid = threadIdx.x;
    const int colBase = blockIdx.x * 64;
    const int rowBase = blockIdx.y * 64;
    const float* Bm = (colBase < NW) ? Wk : Wv;
    const int cb = (colBase < NW) ? colBase : colBase - NW;

    const int tx = tid & 15, ty = tid >> 4;
    const int ar = tid >> 2;
    const int ac = (tid & 3) << 2;
    const int br = tid >> 4;
    const int bc = (tid & 15) << 2;

    float acc[4][4];
    #pragma unroll
    for (int i = 0; i < 4; i++)
        #pragma unroll
        for (int j = 0; j < 4; j++) acc[i][j] = 0.f;

    for (int k0 = 0; k0 < K; k0 += 16) {
        const int grow = rowBase + ar;
        float4 a = (grow < M) ? *(const float4*)&A[(size_t)grow * K + k0 + ac]
                              : make_float4(0.f, 0.f, 0.f, 0.f);
        float4 b = *(const float4*)&Bm[(size_t)(k0 + br) * NW + cb + bc];
        As[ac+0][ar] = a.x; As[ac+1][ar] = a.y; As[ac+2][ar] = a.z; As[ac+3][ar] = a.w;
        *(float4*)&Bs[br][bc] = b;
        __syncthreads();

        #pragma unroll
        for (int kk = 0; kk < 16; kk++) {
            float av[4], bv[4];
            #pragma unroll
            for (int i = 0; i < 4; i++) av[i] = As[kk][ty * 4 + i];
            #pragma unroll
            for (int j = 0; j < 4; j++) bv[j] = Bs[kk][tx * 4 + j];
            #pragma unroll
            for (int i = 0; i < 4; i++)
                #pragma unroll
                for (int j = 0; j < 4; j++) acc[i][j] += av[i] * bv[j];
        }
        __syncthreads();
    }

    #pragma unroll
    for (int i = 0; i < 4; i++) {
        const int r = rowBase + ty * 4 + i;
        if (r < M) {
            float4 v; v.x = acc[i][0]; v.y = acc[i][1]; v.z = acc[i][2]; v.w = acc[i][3];
            *(float4*)&g_kv[(size_t)r * NC + colBase + tx * 4] = v;
        }
    }
}

// =====================================================================
// Attention v4: register softmax + NO Q smem stage (Q fragments straight
// from global; warp owns its rows). smem 68.6KB -> 3 CTAs/SM.
// =====================================================================
constexpr int SS_STRIDE = 84;
constexpr int ATTN_SMEM_B =
    (80 * DH + 80 * DH + 128 * SS_STRIDE) * 4;  // 68,608 B

__global__ void __launch_bounds__(256) attn_kernel(
    const float* __restrict__ q,    // (B*N, 320)
    float* __restrict__ sim,        // (B,H,N,77)
    float* __restrict__ o)          // (B*N, 320)
{
    float* Ks = (float*)smem_raw;              // [80][40]
    float* Vs = Ks + 80 * DH;                  // [80][40]
    float* Ss = Vs + 80 * DH;                  // [128][84]

    const int bh = blockIdx.y;
    const int b = bh >> 3;
    const int h = bh & 7;
    const int tid  = threadIdx.x;
    const int lane = tid & 31;
    const int wid  = tid >> 5;
    const int g = lane >> 2;
    const int t = lane & 3;
    const int nBase = blockIdx.x * 128;
    const int m0 = wid * 16;

    // ---- issue Q fragment loads from global (rows are warp-private) ----
    float qf[5][4];
    {
        const float* qb = q + (size_t)(b * Nn + nBase + m0 + g) * ID + h * DH;
        #pragma unroll
        for (int ks = 0; ks < 5; ks++) {
            const int kc = ks * 8;
            qf[ks][0] = qb[kc + t];
            qf[ks][1] = qb[8 * ID + kc + t];
            qf[ks][2] = qb[kc + t + 4];
            qf[ks][3] = qb[8 * ID + kc + t + 4];
        }
    }

    // ---- stage K, V (tf32, rows 77..79 zeroed) ----
    for (int idx = tid; idx < CN * 10; idx += 256) {
        const int r = idx / 10, c4 = (idx - r * 10) * 4;
        const float* base = g_kv + (size_t)(b * CN + r) * (2 * ID) + h * DH + c4;
        *(uint4*)&Ks[r * DH + c4] = tf32x4(*(const float4*)(base));
        *(uint4*)&Vs[r * DH + c4] = tf32x4(*(const float4*)(base + ID));
    }
    if (tid < 120) {
        Ks[CN * DH + tid] = 0.f;
        Vs[CN * DH + tid] = 0.f;
    }
    __syncthreads();

    // ---- QK^T: warp covers 16 rows x 80 cols ----
    float acc[10][4];
    #pragma unroll
    for (int nt = 0; nt < 10; nt++)
        #pragma unroll
        for (int r = 0; r < 4; r++) acc[nt][r] = 0.f;

    #pragma unroll
    for (int ks = 0; ks < 5; ks++) {
        const int kc = ks * 8;
        const uint32_t a0 = f2tf32(qf[ks][0]);
        const uint32_t a1 = f2tf32(qf[ks][1]);
        const uint32_t a2 = f2tf32(qf[ks][2]);
        const uint32_t a3 = f2tf32(qf[ks][3]);
        #pragma unroll
        for (int nt = 0; nt < 10; nt++) {
            const int n0 = nt * 8 + g;
            uint32_t b0 = __float_as_uint(Ks[n0 * DH + kc + t    ]);
            uint32_t b1 = __float_as_uint(Ks[n0 * DH + kc + t + 4]);
            MMA_TF32(acc[nt], a0, a1, a2, a3, b0, b1);
        }
    }
    // scale
    #pragma unroll
    for (int nt = 0; nt < 10; nt++)
        #pragma unroll
        for (int r = 0; r < 4; r++) acc[nt][r] *= SCALE;

    // ---- sim write straight from registers (scalar stores: stride 77) ----
    {
        float* s0 = sim + ((size_t)bh * Nn + nBase + m0 + g) * CN;
        float* s1 = s0 + 8 * (size_t)CN;
        #pragma unroll
        for (int nt = 0; nt < 10; nt++) {
            const int c = nt * 8 + 2 * t;
            if (c < CN) {
                s0[c] = acc[nt][0];
                s1[c] = acc[nt][2];
            }
            if (c + 1 < CN) {
                s0[c + 1] = acc[nt][1];
                s1[c + 1] = acc[nt][3];
            }
        }
    }

    // ---- softmax in registers ----
    {
        const bool in0 = (t <= 2);   // nt==9 comp0 col = 72+2t < 77
        const bool in1 = (t <= 1);   // nt==9 comp1 col = 73+2t < 77
        float mx0 = -1e30f, mx1 = -1e30f;
        #pragma unroll
        for (int nt = 0; nt < 9; nt++) {
            mx0 = fmaxf(mx0, fmaxf(acc[nt][0], acc[nt][1]));
            mx1 = fmaxf(mx1, fmaxf(acc[nt][2], acc[nt][3]));
        }
        if (in0) { mx0 = fmaxf(mx0, acc[9][0]); mx1 = fmaxf(mx1, acc[9][2]); }
        if (in1) { mx0 = fmaxf(mx0, acc[9][1]); mx1 = fmaxf(mx1, acc[9][3]); }
        mx0 = fmaxf(mx0, __shfl_xor_sync(0xFFFFFFFF, mx0, 1));
        mx0 = fmaxf(mx0, __shfl_xor_sync(0xFFFFFFFF, mx0, 2));
        mx1 = fmaxf(mx1, __shfl_xor_sync(0xFFFFFFFF, mx1, 1));
        mx1 = fmaxf(mx1, __shfl_xor_sync(0xFFFFFFFF, mx1, 2));

        float s0 = 0.f, s1 = 0.f;
        #pragma unroll
        for (int nt = 0; nt < 10; nt++) {
            float e0 = fast_exp(acc[nt][0] - mx0);
            float e1 = fast_exp(acc[nt][1] - mx0);
            float e2 = fast_exp(acc[nt][2] - mx1);
            float e3 = fast_exp(acc[nt][3] - mx1);
            if (nt == 9) {
                if (!in0) { e0 = 0.f; e2 = 0.f; }
                if (!in1) { e1 = 0.f; e3 = 0.f; }
            }
            acc[nt][0] = e0; acc[nt][1] = e1;
            acc[nt][2] = e2; acc[nt][3] = e3;
            s0 += e0 + e1;
            s1 += e2 + e3;
        }
        s0 += __shfl_xor_sync(0xFFFFFFFF, s0, 1);
        s0 += __shfl_xor_sync(0xFFFFFFFF, s0, 2);
        s1 += __shfl_xor_sync(0xFFFFFFFF, s1, 1);
        s1 += __shfl_xor_sync(0xFFFFFFFF, s1, 2);
        const float inv0 = 1.f / s0;
        const float inv1 = 1.f / s1;

        // token-2 reweight: col 2 = nt0, comp0, t==1
        float w = 1.f;
        if (b == 3) w = -2.f; else if (b == 5) w = 5.f;
        if (t == 1) { acc[0][0] *= w; acc[0][2] *= w; }

        // store normalized, tf32-rounded P
        float* p0 = &Ss[(m0 + g    ) * SS_STRIDE + 2 * t];
        float* p1 = &Ss[(m0 + g + 8) * SS_STRIDE + 2 * t];
        #pragma unroll
        for (int nt = 0; nt < 10; nt++) {
            float2 lo, hi;
            lo.x = __uint_as_float(f2tf32(acc[nt][0] * inv0));
            lo.y = __uint_as_float(f2tf32(acc[nt][1] * inv0));
            hi.x = __uint_as_float(f2tf32(acc[nt][2] * inv1));
            hi.y = __uint_as_float(f2tf32(acc[nt][3] * inv1));
            *(float2*)(p0 + nt * 8) = lo;
            *(float2*)(p1 + nt * 8) = hi;
        }
    }
    __syncthreads();

    // ---- P V: warp w -> rows m0..m0+15; N=40 (5 n-tiles); K=80 ----
    {
        float oacc[5][4];
        #pragma unroll
        for (int nt = 0; nt < 5; nt++)
            #pragma unroll
            for (int r = 0; r < 4; r++) oacc[nt][r] = 0.f;

        #pragma unroll
        for (int ks = 0; ks < 10; ks++) {
            const int kc = ks * 8;
            uint32_t a0, a1, a2, a3;
            a0 = __float_as_uint(Ss[(m0 + g    ) * SS_STRIDE + kc + t    ]);
            a1 = __float_as_uint(Ss[(m0 + g + 8) * SS_STRIDE + kc + t    ]);
            a2 = __float_as_uint(Ss[(m0 + g    ) * SS_STRIDE + kc + t + 4]);
            a3 = __float_as_uint(Ss[(m0 + g + 8) * SS_STRIDE + kc + t + 4]);
            #pragma unroll
            for (int nt = 0; nt < 5; nt++) {
                const int n0 = nt * 8 + g;
                uint32_t b0 = __float_as_uint(Vs[(kc + t    ) * DH + n0]);
                uint32_t b1 = __float_as_uint(Vs[(kc + t + 4) * DH + n0]);
                MMA_TF32(oacc[nt], a0, a1, a2, a3, b0, b1);
            }
        }

        float* o0 = o + ((size_t)(b * Nn + nBase + m0 + g    )) * ID + h * DH;
        float* o1 = o + ((size_t)(b * Nn + nBase + m0 + g + 8)) * ID + h * DH;
        #pragma unroll
        for (int nt = 0; nt < 5; nt++) {
            const int c = nt * 8 + 2 * t;
            float2 lo, hi;
            lo.x = oacc[nt][0]; lo.y = oacc[nt][1];
            hi.x = oacc[nt][2]; hi.y = oacc[nt][3];
            *(float2*)(o0 + c) = lo;
            *(float2*)(o1 + c) = hi;
        }
    }
}

// =====================================================================
// launch
// =====================================================================
extern "C" void kernel_launch(void* const* d_in, const int* in_sizes, int n_in,
                              void* d_out, int out_size)
{
    const float* x   = (const float*)d_in[0];
    const float* ctx = (const float*)d_in[1];
    const float* Wq  = (const float*)d_in[2];
    const float* Wk  = (const float*)d_in[3];
    const float* Wv  = (const float*)d_in[4];
    const float* Wo  = (const float*)d_in[5];
    const float* bo  = (const float*)d_in[6];
    // d_in[7] = time (unused: reweight always applies for time >= 0)

    float* out = (float*)d_out;                       // (B, N, 320)
    float* sim = out + (size_t)Bn * Nn * QD;          // (B, H, N, 77)

    float *qp = nullptr, *op = nullptr;
    __half* wt = nullptr;
    cudaGetSymbolAddress((void**)&qp, g_q);
    cudaGetSymbolAddress((void**)&op, g_o);
    cudaGetSymbolAddress((void**)&wt, g_wt);

    cudaFuncSetAttribute(attn_kernel, cudaFuncAttributeMaxDynamicSharedMemorySize,
                         ATTN_SMEM_B);

    // transpose + fp16 convert Wq, Wo
    transpose_w<<<dim3(10, 10, 2), dim3(32, 8)>>>(Wq, Wo);

    // K & V projections (one launch)
    sgemm_kv<<<dim3((2 * ID) / 64, (KVROWS + 63) / 64), 256>>>(ctx, Wk, Wv);

    // Q projection (fp16 tensor cores + ldmatrix)
    gemm_h16<false><<<dim3(320 / 64, MROWS / 128), 128>>>(x, wt, nullptr, qp);

    // fused attention (register softmax, no Q smem stage)
    attn_kernel<<<dim3(Nn / 128, Bn * Hh), 256, ATTN_SMEM_B>>>(qp, sim, op);

    // output projection + bias (fp16 tensor cores + ldmatrix)
    gemm_h16<true><<<dim3(320 / 64, MROWS / 128), 128>>>(op, wt + 320 * 320, bo, out);
}

// round 12
// speedup vs baseline: 2.4785x; 1.0094x over previous
#include <cuda_runtime.h>
#include <cuda_fp16.h>
#include <cstdint>
#include <cstddef>

// ---------------- problem constants ----------------
constexpr int Bn  = 6;
constexpr int Nn  = 4096;
constexpr int QD  = 320;
constexpr int CN  = 77;
constexpr int CD  = 768;
constexpr int Hh  = 8;
constexpr int DH  = 40;
constexpr int ID  = Hh * DH;          // 320 inner dim
constexpr float SCALE = 0.15811388300841897f; // 40^-0.5

constexpr int MROWS = Bn * Nn;        // 24576
constexpr int KVROWS = Bn * CN;       // 462

// single extern shared symbol (attn only)
extern __shared__ char smem_raw[];

// ---------------- scratch (static device memory; no allocs allowed) ------
__device__ float  g_q [ (size_t)MROWS * ID ];     // q projection, (B*N, 320)
__device__ float  g_o [ (size_t)MROWS * ID ];     // attn@v merged heads, (B*N, 320)
__device__ float  g_kv[ (size_t)KVROWS * 2 * ID ];// (B*CN, 640): [0,320)=K, [320,640)=V
__device__ __half g_wt[ 2 * 320 * 320 ];          // Wq^T, Wo^T (fp16, N-major)

// ---------------- helpers ----------------
__device__ __forceinline__ uint32_t smem_u32(const void* p) {
    uint32_t a;
    asm("{ .reg .u64 t; cvta.to.shared.u64 t, %1; cvt.u32.u64 %0, t; }" : "=r"(a) : "l"(p));
    return a;
}
__device__ __forceinline__ uint32_t f2tf32(float f) {
    uint32_t r;
    asm("cvt.rna.tf32.f32 %0, %1;" : "=r"(r) : "f"(f));
    return r;
}
__device__ __forceinline__ uint4 tf32x4(float4 v) {
    uint4 r;
    r.x = f2tf32(v.x); r.y = f2tf32(v.y);
    r.z = f2tf32(v.z); r.w = f2tf32(v.w);
    return r;
}
// FFMA-only exp (relative error ~2.5e-6)
__device__ __forceinline__ float fast_exp(float x) {
    x = fmaxf(x, -60.f);
    float y = x * 1.4426950408889634f;
    int   n = __float2int_rn(y);
    float f = y - (float)n;
    float t = f * 0.6931471805599453f;
    float p = 8.3333333333e-3f;
    p = fmaf(p, t, 4.1666666667e-2f);
    p = fmaf(p, t, 1.6666666667e-1f);
    p = fmaf(p, t, 0.5f);
    p = fmaf(p, t, 1.0f);
    p = fmaf(p, t, 1.0f);
    return __int_as_float(__float_as_int(p) + (n << 23));
}

#define MMA_TF32(acc, a0, a1, a2, a3, b0, b1)                                   \
    asm volatile(                                                               \
        "mma.sync.aligned.m16n8k8.row.col.f32.tf32.tf32.f32 "                   \
        "{%0,%1,%2,%3}, {%4,%5,%6,%7}, {%8,%9}, {%0,%1,%2,%3};\n"               \
        : "+f"(acc[0]), "+f"(acc[1]), "+f"(acc[2]), "+f"(acc[3])                \
        : "r"(a0), "r"(a1), "r"(a2), "r"(a3), "r"(b0), "r"(b1))

#define MMA_F16(acc, a0, a1, a2, a3, b0, b1)                                    \
    asm volatile(                                                               \
        "mma.sync.aligned.m16n8k16.row.col.f32.f16.f16.f32 "                    \
        "{%0,%1,%2,%3}, {%4,%5,%6,%7}, {%8,%9}, {%0,%1,%2,%3};\n"               \
        : "+f"(acc[0]), "+f"(acc[1]), "+f"(acc[2]), "+f"(acc[3])                \
        : "r"(a0), "r"(a1), "r"(a2), "r"(a3), "r"(b0), "r"(b1))

#define LDMATRIX_X4(r0, r1, r2, r3, addr)                                       \
    asm volatile("ldmatrix.sync.aligned.m8n8.x4.shared.b16 {%0,%1,%2,%3}, [%4];"\
        : "=r"(r0), "=r"(r1), "=r"(r2), "=r"(r3) : "r"(addr))

// =====================================================================
// W transpose + fp16 convert: g_wt[sel][n][k] = half(W[k][n]), 320x320
// =====================================================================
__global__ void transpose_w(const float* __restrict__ Wq, const float* __restrict__ Wo)
{
    __shared__ float tile[32][33];
    const float* W = (blockIdx.z == 0) ? Wq : Wo;
    __half* Wt = g_wt + (size_t)blockIdx.z * 320 * 320;
    const int kBase = blockIdx.y * 32;
    const int nBase = blockIdx.x * 32;
    const int tx = threadIdx.x, ty = threadIdx.y;  // (32, 8)
    #pragma unroll
    for (int i = 0; i < 4; i++)
        tile[ty + 8 * i][tx] = W[(size_t)(kBase + ty + 8 * i) * 320 + nBase + tx];
    __syncthreads();
    #pragma unroll
    for (int i = 0; i < 4; i++)
        Wt[(size_t)(nBase + ty + 8 * i) * 320 + kBase + tx] =
            __float2half_rn(tile[tx][ty + 8 * i]);
}

// =====================================================================
// FP16 tensor-core GEMM v3.1: C(24576x320) = A @ W (+bias), fp32 acc.
// BM=128, BN=64, BK=32, 128 threads (4 warps 2Mx2N, warp 64x32).
// ldmatrix.x4 fragments; smem stride 40 halves -> LDSM conflict-free.
// FIX vs v3: B staging now uint4 (8 halves) per thread -> full coverage.
// =====================================================================
template<bool BIAS>
__global__ void __launch_bounds__(128) gemm_h16(
    const float*  __restrict__ A,      // (24576, 320) fp32
    const __half* __restrict__ Wt,     // (320, 320) N-major fp16
    const float*  __restrict__ bias,   // (320) or null
    float* __restrict__ C)             // (24576, 320)
{
    constexpr int Nc = 320, K = 320;
    constexpr int BK = 32;
    constexpr int HS = 40;             // half stride (pad 32 -> 40)

    __shared__ __half Ah[128][HS];     // 10,240 B
    __shared__ __half Bh[64][HS];      //  5,120 B

    const int tid  = threadIdx.x;
    const int lane = tid & 31;
    const int wid  = tid >> 5;
    const int warpM = wid & 1;
    const int warpN = wid >> 1;
    const int g = lane >> 2;
    const int t = lane & 3;
    const int lrow = lane & 7;
    const int lgrp = lane >> 3;        // 0..3

    const int rowBase = blockIdx.y * 128;
    const int colBase = blockIdx.x * 64;

    // staging maps
    const int sr  = tid >> 3;          // 0..15, A rows step 16
    const int sc4 = (tid & 7) * 4;     // A float col (4 floats -> 4 halves)
    const int br  = tid >> 2;          // 0..31, B rows step 32
    const int bc  = (tid & 3) * 8;     // B half col (8 halves = uint4)

    const float*  aPtr = A  + (size_t)(rowBase + sr) * K + sc4;
    const __half* bPtr = Wt + (size_t)(colBase + br) * K + bc;

    float4 aR[8];
    uint4  bR[2];
    #pragma unroll
    for (int i = 0; i < 8; i++) aR[i] = *(const float4*)(aPtr + (size_t)(16 * i) * K);
    bR[0] = *(const uint4*)(bPtr);
    bR[1] = *(const uint4*)(bPtr + (size_t)32 * K);

    float acc[4][4][4];
    #pragma unroll
    for (int mt = 0; mt < 4; mt++)
        #pragma unroll
        for (int nt = 0; nt < 4; nt++)
            #pragma unroll
            for (int r = 0; r < 4; r++) acc[mt][nt][r] = 0.f;

    // ldmatrix lane address components
    const int a_row = (lgrp & 1) * 8 + lrow;     // + mt*16 + warpM*64
    const int a_col = (lgrp >> 1) * 8;           // + kc
    const int b_row = (lgrp >> 1) * 8 + lrow;    // + nb*16 + warpN*32
    const int b_col = (lgrp & 1) * 8;            // + kc

    for (int k0 = 0; k0 < K; k0 += BK) {
        // store staged tiles (A fp32 -> fp16; B already fp16)
        #pragma unroll
        for (int i = 0; i < 8; i++) {
            float4 v = aR[i];
            __half2 h0 = __floats2half2_rn(v.x, v.y);
            __half2 h1 = __floats2half2_rn(v.z, v.w);
            uint2 u;
            u.x = *(const uint32_t*)&h0;
            u.y = *(const uint32_t*)&h1;
            *(uint2*)&Ah[sr + 16 * i][sc4] = u;
        }
        *(uint4*)&Bh[br][bc]      = bR[0];
        *(uint4*)&Bh[br + 32][bc] = bR[1];
        __syncthreads();

        // prefetch next stage
        if (k0 + BK < K) {
            #pragma unroll
            for (int i = 0; i < 8; i++)
                aR[i] = *(const float4*)(aPtr + (size_t)(16 * i) * K + k0 + BK);
            bR[0] = *(const uint4*)(bPtr + k0 + BK);
            bR[1] = *(const uint4*)(bPtr + (size_t)32 * K + k0 + BK);
        }

        #pragma unroll
        for (int kk = 0; kk < 2; kk++) {
            const int kc = kk * 16;
            uint32_t afr[4][4], bfr[4][2];
            #pragma unroll
            for (int mt = 0; mt < 4; mt++) {
                uint32_t addr = smem_u32(&Ah[warpM * 64 + mt * 16 + a_row][kc + a_col]);
                LDMATRIX_X4(afr[mt][0], afr[mt][1], afr[mt][2], afr[mt][3], addr);
            }
            #pragma unroll
            for (int nb = 0; nb < 2; nb++) {
                uint32_t addr = smem_u32(&Bh[warpN * 32 + nb * 16 + b_row][kc + b_col]);
                LDMATRIX_X4(bfr[2 * nb][0], bfr[2 * nb][1],
                            bfr[2 * nb + 1][0], bfr[2 * nb + 1][1], addr);
            }
            #pragma unroll
            for (int mt = 0; mt < 4; mt++)
                #pragma unroll
                for (int nt = 0; nt < 4; nt++)
                    MMA_F16(acc[mt][nt], afr[mt][0], afr[mt][1], afr[mt][2], afr[mt][3],
                            bfr[nt][0], bfr[nt][1]);
        }
        __syncthreads();
    }

    // epilogue
    #pragma unroll
    for (int mt = 0; mt < 4; mt++) {
        const int row = rowBase + warpM * 64 + mt * 16 + g;
        #pragma unroll
        for (int nt = 0; nt < 4; nt++) {
            const int col = colBase + warpN * 32 + nt * 8 + 2 * t;
            float b0 = 0.f, b1 = 0.f;
            if (BIAS) { b0 = bias[col]; b1 = bias[col + 1]; }
            float2 lo, hi;
            lo.x = acc[mt][nt][0] + b0; lo.y = acc[mt][nt][1] + b1;
            hi.x = acc[mt][nt][2] + b0; hi.y = acc[mt][nt][3] + b1;
            *(float2*)&C[(size_t)row * Nc + col]       = lo;
            *(float2*)&C[(size_t)(row + 8) * Nc + col] = hi;
        }
    }
}

// =====================================================================
// K/V projection in ONE launch (fp32 FFMA; tiny: 462x640x768)
// =====================================================================
__global__ void __launch_bounds__(256) sgemm_kv(
    const float* __restrict__ A,
    const float* __restrict__ Wk,
    const float* __restrict__ Wv)
{
    constexpr int M = KVROWS, K = CD, NW = ID, NC = 2 * ID;
    __shared__ float As[16][64 + 4];
    __shared__ float Bs[16][64];

    const int tid = threadIdx.x;
    const int colBase = blockIdx.x * 64;
    const int rowBase = blockIdx.y * 64;
    const float* Bm = (colBase < NW) ? Wk : Wv;
    const int cb = (colBase < NW) ? colBase : colBase - NW;

    const int tx = tid & 15, ty = tid >> 4;
    const int ar = tid >> 2;
    const int ac = (tid & 3) << 2;
    const int br = tid >> 4;
    const int bc = (tid & 15) << 2;

    float acc[4][4];
    #pragma unroll
    for (int i = 0; i < 4; i++)
        #pragma unroll
        for (int j = 0; j < 4; j++) acc[i][j] = 0.f;

    for (int k0 = 0; k0 < K; k0 += 16) {
        const int grow = rowBase + ar;
        float4 a = (grow < M) ? *(const float4*)&A[(size_t)grow * K + k0 + ac]
                              : make_float4(0.f, 0.f, 0.f, 0.f);
        float4 b = *(const float4*)&Bm[(size_t)(k0 + br) * NW + cb + bc];
        As[ac+0][ar] = a.x; As[ac+1][ar] = a.y; As[ac+2][ar] = a.z; As[ac+3][ar] = a.w;
        *(float4*)&Bs[br][bc] = b;
        __syncthreads();

        #pragma unroll
        for (int kk = 0; kk < 16; kk++) {
            float av[4], bv[4];
            #pragma unroll
            for (int i = 0; i < 4; i++) av[i] = As[kk][ty * 4 + i];
            #pragma unroll
            for (int j = 0; j < 4; j++) bv[j] = Bs[kk][tx * 4 + j];
            #pragma unroll
            for (int i = 0; i < 4; i++)
                #pragma unroll
                for (int j = 0; j < 4; j++) acc[i][j] += av[i] * bv[j];
        }
        __syncthreads();
    }

    #pragma unroll
    for (int i = 0; i < 4; i++) {
        const int r = rowBase + ty * 4 + i;
        if (r < M) {
            float4 v; v.x = acc[i][0]; v.y = acc[i][1]; v.z = acc[i][2]; v.w = acc[i][3];
            *(float4*)&g_kv[(size_t)r * NC + colBase + tx * 4] = v;
        }
    }
}

// =====================================================================
// Attention v4: register softmax + NO Q smem stage (Q fragments straight
// from global; warp owns its rows). smem 68.6KB -> 3 CTAs/SM.
// =====================================================================
constexpr int SS_STRIDE = 84;
constexpr int ATTN_SMEM_B =
    (80 * DH + 80 * DH + 128 * SS_STRIDE) * 4;  // 68,608 B

__global__ void __launch_bounds__(256) attn_kernel(
    const float* __restrict__ q,    // (B*N, 320)
    float* __restrict__ sim,        // (B,H,N,77)
    float* __restrict__ o)          // (B*N, 320)
{
    float* Ks = (float*)smem_raw;              // [80][40]
    float* Vs = Ks + 80 * DH;                  // [80][40]
    float* Ss = Vs + 80 * DH;                  // [128][84]

    const int bh = blockIdx.y;
    const int b = bh >> 3;
    const int h = bh & 7;
    const int tid  = threadIdx.x;
    const int lane = tid & 31;
    const int wid  = tid >> 5;
    const int g = lane >> 2;
    const int t = lane & 3;
    const int nBase = blockIdx.x * 128;
    const int m0 = wid * 16;

    // ---- issue Q fragment loads from global (rows are warp-private) ----
    float qf[5][4];
    {
        const float* qb = q + (size_t)(b * Nn + nBase + m0 + g) * ID + h * DH;
        #pragma unroll
        for (int ks = 0; ks < 5; ks++) {
            const int kc = ks * 8;
            qf[ks][0] = qb[kc + t];
            qf[ks][1] = qb[8 * ID + kc + t];
            qf[ks][2] = qb[kc + t + 4];
            qf[ks][3] = qb[8 * ID + kc + t + 4];
        }
    }

    // ---- stage K, V (tf32, rows 77..79 zeroed) ----
    for (int idx = tid; idx < CN * 10; idx += 256) {
        const int r = idx / 10, c4 = (idx - r * 10) * 4;
        const float* base = g_kv + (size_t)(b * CN + r) * (2 * ID) + h * DH + c4;
        *(uint4*)&Ks[r * DH + c4] = tf32x4(*(const float4*)(base));
        *(uint4*)&Vs[r * DH + c4] = tf32x4(*(const float4*)(base + ID));
    }
    if (tid < 120) {
        Ks[CN * DH + tid] = 0.f;
        Vs[CN * DH + tid] = 0.f;
    }
    __syncthreads();

    // ---- QK^T: warp covers 16 rows x 80 cols ----
    float acc[10][4];
    #pragma unroll
    for (int nt = 0; nt < 10; nt++)
        #pragma unroll
        for (int r = 0; r < 4; r++) acc[nt][r] = 0.f;

    #pragma unroll
    for (int ks = 0; ks < 5; ks++) {
        const int kc = ks * 8;
        const uint32_t a0 = f2tf32(qf[ks][0]);
        const uint32_t a1 = f2tf32(qf[ks][1]);
        const uint32_t a2 = f2tf32(qf[ks][2]);
        const uint32_t a3 = f2tf32(qf[ks][3]);
        #pragma unroll
        for (int nt = 0; nt < 10; nt++) {
            const int n0 = nt * 8 + g;
            uint32_t b0 = __float_as_uint(Ks[n0 * DH + kc + t    ]);
            uint32_t b1 = __float_as_uint(Ks[n0 * DH + kc + t + 4]);
            MMA_TF32(acc[nt], a0, a1, a2, a3, b0, b1);
        }
    }
    // scale
    #pragma unroll
    for (int nt = 0; nt < 10; nt++)
        #pragma unroll
        for (int r = 0; r < 4; r++) acc[nt][r] *= SCALE;

    // ---- sim write straight from registers (scalar stores: stride 77) ----
    {
        float* s0 = sim + ((size_t)bh * Nn + nBase + m0 + g) * CN;
        float* s1 = s0 + 8 * (size_t)CN;
        #pragma unroll
        for (int nt = 0; nt < 10; nt++) {
            const int c = nt * 8 + 2 * t;
            if (c < CN) {
                s0[c] = acc[nt][0];
                s1[c] = acc[nt][2];
            }
            if (c + 1 < CN) {
                s0[c + 1] = acc[nt][1];
                s1[c + 1] = acc[nt][3];
            }
        }
    }

    // ---- softmax in registers ----
    {
        const bool in0 = (t <= 2);   // nt==9 comp0 col = 72+2t < 77
        const bool in1 = (t <= 1);   // nt==9 comp1 col = 73+2t < 77
        float mx0 = -1e30f, mx1 = -1e30f;
        #pragma unroll
        for (int nt = 0; nt < 9; nt++) {
            mx0 = fmaxf(mx0, fmaxf(acc[nt][0], acc[nt][1]));
            mx1 = fmaxf(mx1, fmaxf(acc[nt][2], acc[nt][3]));
        }
        if (in0) { mx0 = fmaxf(mx0, acc[9][0]); mx1 = fmaxf(mx1, acc[9][2]); }
        if (in1) { mx0 = fmaxf(mx0, acc[9][1]); mx1 = fmaxf(mx1, acc[9][3]); }
        mx0 = fmaxf(mx0, __shfl_xor_sync(0xFFFFFFFF, mx0, 1));
        mx0 = fmaxf(mx0, __shfl_xor_sync(0xFFFFFFFF, mx0, 2));
        mx1 = fmaxf(mx1, __shfl_xor_sync(0xFFFFFFFF, mx1, 1));
        mx1 = fmaxf(mx1, __shfl_xor_sync(0xFFFFFFFF, mx1, 2));

        float s0 = 0.f, s1 = 0.f;
        #pragma unroll
        for (int nt = 0; nt < 10; nt++) {
            float e0 = fast_exp(acc[nt][0] - mx0);
            float e1 = fast_exp(acc[nt][1] - mx0);
            float e2 = fast_exp(acc[nt][2] - mx1);
            float e3 = fast_exp(acc[nt][3] - mx1);
            if (nt == 9) {
                if (!in0) { e0 = 0.f; e2 = 0.f; }
                if (!in1) { e1 = 0.f; e3 = 0.f; }
            }
            acc[nt][0] = e0; acc[nt][1] = e1;
            acc[nt][2] = e2; acc[nt][3] = e3;
            s0 += e0 + e1;
            s1 += e2 + e3;
        }
        s0 += __shfl_xor_sync(0xFFFFFFFF, s0, 1);
        s0 += __shfl_xor_sync(0xFFFFFFFF, s0, 2);
        s1 += __shfl_xor_sync(0xFFFFFFFF, s1, 1);
        s1 += __shfl_xor_sync(0xFFFFFFFF, s1, 2);
        const float inv0 = 1.f / s0;
        const float inv1 = 1.f / s1;

        // token-2 reweight: col 2 = nt0, comp0, t==1
        float w = 1.f;
        if (b == 3) w = -2.f; else if (b == 5) w = 5.f;
        if (t == 1) { acc[0][0] *= w; acc[0][2] *= w; }

        // store normalized, tf32-rounded P
        float* p0 = &Ss[(m0 + g    ) * SS_STRIDE + 2 * t];
        float* p1 = &Ss[(m0 + g + 8) * SS_STRIDE + 2 * t];
        #pragma unroll
        for (int nt = 0; nt < 10; nt++) {
            float2 lo, hi;
            lo.x = __uint_as_float(f2tf32(acc[nt][0] * inv0));
            lo.y = __uint_as_float(f2tf32(acc[nt][1] * inv0));
            hi.x = __uint_as_float(f2tf32(acc[nt][2] * inv1));
            hi.y = __uint_as_float(f2tf32(acc[nt][3] * inv1));
            *(float2*)(p0 + nt * 8) = lo;
            *(float2*)(p1 + nt * 8) = hi;
        }
    }
    __syncthreads();

    // ---- P V: warp w -> rows m0..m0+15; N=40 (5 n-tiles); K=80 ----
    {
        float oacc[5][4];
        #pragma unroll
        for (int nt = 0; nt < 5; nt++)
            #pragma unroll
            for (int r = 0; r < 4; r++) oacc[nt][r] = 0.f;

        #pragma unroll
        for (int ks = 0; ks < 10; ks++) {
            const int kc = ks * 8;
            uint32_t a0, a1, a2, a3;
            a0 = __float_as_uint(Ss[(m0 + g    ) * SS_STRIDE + kc + t    ]);
            a1 = __float_as_uint(Ss[(m0 + g + 8) * SS_STRIDE + kc + t    ]);
            a2 = __float_as_uint(Ss[(m0 + g    ) * SS_STRIDE + kc + t + 4]);
            a3 = __float_as_uint(Ss[(m0 + g + 8) * SS_STRIDE + kc + t + 4]);
            #pragma unroll
            for (int nt = 0; nt < 5; nt++) {
                const int n0 = nt * 8 + g;
                uint32_t b0 = __float_as_uint(Vs[(kc + t    ) * DH + n0]);
                uint32_t b1 = __float_as_uint(Vs[(kc + t + 4) * DH + n0]);
                MMA_TF32(oacc[nt], a0, a1, a2, a3, b0, b1);
            }
        }

        float* o0 = o + ((size_t)(b * Nn + nBase + m0 + g    )) * ID + h * DH;
        float* o1 = o + ((size_t)(b * Nn + nBase + m0 + g + 8)) * ID + h * DH;
        #pragma unroll
        for (int nt = 0; nt < 5; nt++) {
            const int c = nt * 8 + 2 * t;
            float2 lo, hi;
            lo.x = oacc[nt][0]; lo.y = oacc[nt][1];
            hi.x = oacc[nt][2]; hi.y = oacc[nt][3];
            *(float2*)(o0 + c) = lo;
            *(float2*)(o1 + c) = hi;
        }
    }
}

// =====================================================================
// launch
// =====================================================================
extern "C" void kernel_launch(void* const* d_in, const int* in_sizes, int n_in,
                              void* d_out, int out_size)
{
    const float* x   = (const float*)d_in[0];
    const float* ctx = (const float*)d_in[1];
    const float* Wq  = (const float*)d_in[2];
    const float* Wk  = (const float*)d_in[3];
    const float* Wv  = (const float*)d_in[4];
    const float* Wo  = (const float*)d_in[5];
    const float* bo  = (const float*)d_in[6];
    // d_in[7] = time (unused: reweight always applies for time >= 0)

    float* out = (float*)d_out;                       // (B, N, 320)
    float* sim = out + (size_t)Bn * Nn * QD;          // (B, H, N, 77)

    float *qp = nullptr, *op = nullptr;
    __half* wt = nullptr;
    cudaGetSymbolAddress((void**)&qp, g_q);
    cudaGetSymbolAddress((void**)&op, g_o);
    cudaGetSymbolAddress((void**)&wt, g_wt);

    cudaFuncSetAttribute(attn_kernel, cudaFuncAttributeMaxDynamicSharedMemorySize,
                         ATTN_SMEM_B);

    // transpose + fp16 convert Wq, Wo
    transpose_w<<<dim3(10, 10, 2), dim3(32, 8)>>>(Wq, Wo);

    // K & V projections (one launch)
    sgemm_kv<<<dim3((2 * ID) / 64, (KVROWS + 63) / 64), 256>>>(ctx, Wk, Wv);

    // Q projection (fp16 tensor cores + ldmatrix)
    gemm_h16<false><<<dim3(320 / 64, MROWS / 128), 128>>>(x, wt, nullptr, qp);

    // fused attention (register softmax, no Q smem stage)
    attn_kernel<<<dim3(Nn / 128, Bn * Hh), 256, ATTN_SMEM_B>>>(qp, sim, op);

    // output projection + bias (fp16 tensor cores + ldmatrix)
    gemm_h16<true><<<dim3(320 / 64, MROWS / 128), 128>>>(op, wt + 320 * 320, bo, out);
}

// round 13
// speedup vs baseline: 2.5605x; 1.0331x over previous
#include <cuda_runtime.h>
#include <cuda_fp16.h>
#include <cstdint>
#include <cstddef>

// ---------------- problem constants ----------------
constexpr int Bn  = 6;
constexpr int Nn  = 4096;
constexpr int QD  = 320;
constexpr int CN  = 77;
constexpr int CD  = 768;
constexpr int Hh  = 8;
constexpr int DH  = 40;
constexpr int ID  = Hh * DH;          // 320 inner dim
constexpr float SCALE = 0.15811388300841897f; // 40^-0.5

constexpr int MROWS = Bn * Nn;        // 24576
constexpr int KVROWS = Bn * CN;       // 462

// single extern shared symbol (attn only)
extern __shared__ char smem_raw[];

// ---------------- scratch (static device memory; no allocs allowed) ------
__device__ float  g_q [ (size_t)MROWS * ID ];     // q projection, (B*N, 320)
__device__ float  g_o [ (size_t)MROWS * ID ];     // attn@v merged heads, (B*N, 320)
__device__ float  g_kv[ (size_t)KVROWS * 2 * ID ];// (B*CN, 640): [0,320)=K, [320,640)=V
__device__ __half g_wt[ 2 * 320 * 320 ];          // Wq^T, Wo^T (fp16, N-major)

// ---------------- helpers ----------------
__device__ __forceinline__ uint32_t smem_u32(const void* p) {
    uint32_t a;
    asm("{ .reg .u64 t; cvta.to.shared.u64 t, %1; cvt.u32.u64 %0, t; }" : "=r"(a) : "l"(p));
    return a;
}
__device__ __forceinline__ uint32_t f2tf32(float f) {
    uint32_t r;
    asm("cvt.rna.tf32.f32 %0, %1;" : "=r"(r) : "f"(f));
    return r;
}
__device__ __forceinline__ uint4 tf32x4(float4 v) {
    uint4 r;
    r.x = f2tf32(v.x); r.y = f2tf32(v.y);
    r.z = f2tf32(v.z); r.w = f2tf32(v.w);
    return r;
}
// FFMA-only exp (relative error ~2.5e-6)
__device__ __forceinline__ float fast_exp(float x) {
    x = fmaxf(x, -60.f);
    float y = x * 1.4426950408889634f;
    int   n = __float2int_rn(y);
    float f = y - (float)n;
    float t = f * 0.6931471805599453f;
    float p = 8.3333333333e-3f;
    p = fmaf(p, t, 4.1666666667e-2f);
    p = fmaf(p, t, 1.6666666667e-1f);
    p = fmaf(p, t, 0.5f);
    p = fmaf(p, t, 1.0f);
    p = fmaf(p, t, 1.0f);
    return __int_as_float(__float_as_int(p) + (n << 23));
}

#define MMA_TF32(acc, a0, a1, a2, a3, b0, b1)                                   \
    asm volatile(                                                               \
        "mma.sync.aligned.m16n8k8.row.col.f32.tf32.tf32.f32 "                   \
        "{%0,%1,%2,%3}, {%4,%5,%6,%7}, {%8,%9}, {%0,%1,%2,%3};\n"               \
        : "+f"(acc[0]), "+f"(acc[1]), "+f"(acc[2]), "+f"(acc[3])                \
        : "r"(a0), "r"(a1), "r"(a2), "r"(a3), "r"(b0), "r"(b1))

#define MMA_F16(acc, a0, a1, a2, a3, b0, b1)                                    \
    asm volatile(                                                               \
        "mma.sync.aligned.m16n8k16.row.col.f32.f16.f16.f32 "                    \
        "{%0,%1,%2,%3}, {%4,%5,%6,%7}, {%8,%9}, {%0,%1,%2,%3};\n"               \
        : "+f"(acc[0]), "+f"(acc[1]), "+f"(acc[2]), "+f"(acc[3])                \
        : "r"(a0), "r"(a1), "r"(a2), "r"(a3), "r"(b0), "r"(b1))

#define LDMATRIX_X4(r0, r1, r2, r3, addr)                                       \
    asm volatile("ldmatrix.sync.aligned.m8n8.x4.shared.b16 {%0,%1,%2,%3}, [%4];"\
        : "=r"(r0), "=r"(r1), "=r"(r2), "=r"(r3) : "r"(addr))

// =====================================================================
// W transpose + fp16 convert: g_wt[sel][n][k] = half(W[k][n]), 320x320
// =====================================================================
__global__ void transpose_w(const float* __restrict__ Wq, const float* __restrict__ Wo)
{
    __shared__ float tile[32][33];
    const float* W = (blockIdx.z == 0) ? Wq : Wo;
    __half* Wt = g_wt + (size_t)blockIdx.z * 320 * 320;
    const int kBase = blockIdx.y * 32;
    const int nBase = blockIdx.x * 32;
    const int tx = threadIdx.x, ty = threadIdx.y;  // (32, 8)
    #pragma unroll
    for (int i = 0; i < 4; i++)
        tile[ty + 8 * i][tx] = W[(size_t)(kBase + ty + 8 * i) * 320 + nBase + tx];
    __syncthreads();
    #pragma unroll
    for (int i = 0; i < 4; i++)
        Wt[(size_t)(nBase + ty + 8 * i) * 320 + kBase + tx] =
            __float2half_rn(tile[tx][ty + 8 * i]);
}

// =====================================================================
// FP16 tensor-core GEMM (R12-proven): 128x64 tile, 128 thr, warp 64x32,
// ldmatrix.x4, smem stride 40 halves conflict-free.
// =====================================================================
template<bool BIAS>
__global__ void __launch_bounds__(128) gemm_h16(
    const float*  __restrict__ A,      // (24576, 320) fp32
    const __half* __restrict__ Wt,     // (320, 320) N-major fp16
    const float*  __restrict__ bias,   // (320) or null
    float* __restrict__ C)             // (24576, 320)
{
    constexpr int Nc = 320, K = 320;
    constexpr int BK = 32;
    constexpr int HS = 40;

    __shared__ __half Ah[128][HS];
    __shared__ __half Bh[64][HS];

    const int tid  = threadIdx.x;
    const int lane = tid & 31;
    const int wid  = tid >> 5;
    const int warpM = wid & 1;
    const int warpN = wid >> 1;
    const int g = lane >> 2;
    const int t = lane & 3;
    const int lrow = lane & 7;
    const int lgrp = lane >> 3;

    const int rowBase = blockIdx.y * 128;
    const int colBase = blockIdx.x * 64;

    const int sr  = tid >> 3;
    const int sc4 = (tid & 7) * 4;
    const int br  = tid >> 2;
    const int bc  = (tid & 3) * 8;

    const float*  aPtr = A  + (size_t)(rowBase + sr) * K + sc4;
    const __half* bPtr = Wt + (size_t)(colBase + br) * K + bc;

    float4 aR[8];
    uint4  bR[2];
    #pragma unroll
    for (int i = 0; i < 8; i++) aR[i] = *(const float4*)(aPtr + (size_t)(16 * i) * K);
    bR[0] = *(const uint4*)(bPtr);
    bR[1] = *(const uint4*)(bPtr + (size_t)32 * K);

    float acc[4][4][4];
    #pragma unroll
    for (int mt = 0; mt < 4; mt++)
        #pragma unroll
        for (int nt = 0; nt < 4; nt++)
            #pragma unroll
            for (int r = 0; r < 4; r++) acc[mt][nt][r] = 0.f;

    const int a_row = (lgrp & 1) * 8 + lrow;
    const int a_col = (lgrp >> 1) * 8;
    const int b_row = (lgrp >> 1) * 8 + lrow;
    const int b_col = (lgrp & 1) * 8;

    for (int k0 = 0; k0 < K; k0 += BK) {
        #pragma unroll
        for (int i = 0; i < 8; i++) {
            float4 v = aR[i];
            __half2 h0 = __floats2half2_rn(v.x, v.y);
            __half2 h1 = __floats2half2_rn(v.z, v.w);
            uint2 u;
            u.x = *(const uint32_t*)&h0;
            u.y = *(const uint32_t*)&h1;
            *(uint2*)&Ah[sr + 16 * i][sc4] = u;
        }
        *(uint4*)&Bh[br][bc]      = bR[0];
        *(uint4*)&Bh[br + 32][bc] = bR[1];
        __syncthreads();

        if (k0 + BK < K) {
            #pragma unroll
            for (int i = 0; i < 8; i++)
                aR[i] = *(const float4*)(aPtr + (size_t)(16 * i) * K + k0 + BK);
            bR[0] = *(const uint4*)(bPtr + k0 + BK);
            bR[1] = *(const uint4*)(bPtr + (size_t)32 * K + k0 + BK);
        }

        #pragma unroll
        for (int kk = 0; kk < 2; kk++) {
            const int kc = kk * 16;
            uint32_t afr[4][4], bfr[4][2];
            #pragma unroll
            for (int mt = 0; mt < 4; mt++) {
                uint32_t addr = smem_u32(&Ah[warpM * 64 + mt * 16 + a_row][kc + a_col]);
                LDMATRIX_X4(afr[mt][0], afr[mt][1], afr[mt][2], afr[mt][3], addr);
            }
            #pragma unroll
            for (int nb = 0; nb < 2; nb++) {
                uint32_t addr = smem_u32(&Bh[warpN * 32 + nb * 16 + b_row][kc + b_col]);
                LDMATRIX_X4(bfr[2 * nb][0], bfr[2 * nb][1],
                            bfr[2 * nb + 1][0], bfr[2 * nb + 1][1], addr);
            }
            #pragma unroll
            for (int mt = 0; mt < 4; mt++)
                #pragma unroll
                for (int nt = 0; nt < 4; nt++)
                    MMA_F16(acc[mt][nt], afr[mt][0], afr[mt][1], afr[mt][2], afr[mt][3],
                            bfr[nt][0], bfr[nt][1]);
        }
        __syncthreads();
    }

    #pragma unroll
    for (int mt = 0; mt < 4; mt++) {
        const int row = rowBase + warpM * 64 + mt * 16 + g;
        #pragma unroll
        for (int nt = 0; nt < 4; nt++) {
            const int col = colBase + warpN * 32 + nt * 8 + 2 * t;
            float b0 = 0.f, b1 = 0.f;
            if (BIAS) { b0 = bias[col]; b1 = bias[col + 1]; }
            float2 lo, hi;
            lo.x = acc[mt][nt][0] + b0; lo.y = acc[mt][nt][1] + b1;
            hi.x = acc[mt][nt][2] + b0; hi.y = acc[mt][nt][3] + b1;
            *(float2*)&C[(size_t)row * Nc + col]       = lo;
            *(float2*)&C[(size_t)(row + 8) * Nc + col] = hi;
        }
    }
}

// =====================================================================
// K/V projection in ONE launch (fp32 FFMA; tiny: 462x640x768)
// =====================================================================
__global__ void __launch_bounds__(256) sgemm_kv(
    const float* __restrict__ A,
    const float* __restrict__ Wk,
    const float* __restrict__ Wv)
{
    constexpr int M = KVROWS, K = CD, NW = ID, NC = 2 * ID;
    __shared__ float As[16][64 + 4];
    __shared__ float Bs[16][64];

    const int tid = threadIdx.x;
    const int colBase = blockIdx.x * 64;
    const int rowBase = blockIdx.y * 64;
    const float* Bm = (colBase < NW) ? Wk : Wv;
    const int cb = (colBase < NW) ? colBase : colBase - NW;

    const int tx = tid & 15, ty = tid >> 4;
    const int ar = tid >> 2;
    const int ac = (tid & 3) << 2;
    const int br = tid >> 4;
    const int bc = (tid & 15) << 2;

    float acc[4][4];
    #pragma unroll
    for (int i = 0; i < 4; i++)
        #pragma unroll
        for (int j = 0; j < 4; j++) acc[i][j] = 0.f;

    for (int k0 = 0; k0 < K; k0 += 16) {
        const int grow = rowBase + ar;
        float4 a = (grow < M) ? *(const float4*)&A[(size_t)grow * K + k0 + ac]
                              : make_float4(0.f, 0.f, 0.f, 0.f);
        float4 b = *(const float4*)&Bm[(size_t)(k0 + br) * NW + cb + bc];
        As[ac+0][ar] = a.x; As[ac+1][ar] = a.y; As[ac+2][ar] = a.z; As[ac+3][ar] = a.w;
        *(float4*)&Bs[br][bc] = b;
        __syncthreads();

        #pragma unroll
        for (int kk = 0; kk < 16; kk++) {
            float av[4], bv[4];
            #pragma unroll
            for (int i = 0; i < 4; i++) av[i] = As[kk][ty * 4 + i];
            #pragma unroll
            for (int j = 0; j < 4; j++) bv[j] = Bs[kk][tx * 4 + j];
            #pragma unroll
            for (int i = 0; i < 4; i++)
                #pragma unroll
                for (int j = 0; j < 4; j++) acc[i][j] += av[i] * bv[j];
        }
        __syncthreads();
    }

    #pragma unroll
    for (int i = 0; i < 4; i++) {
        const int r = rowBase + ty * 4 + i;
        if (r < M) {
            float4 v; v.x = acc[i][0]; v.y = acc[i][1]; v.z = acc[i][2]; v.w = acc[i][3];
            *(float4*)&g_kv[(size_t)r * NC + colBase + tx * 4] = v;
        }
    }
}

// =====================================================================
// Attention v5: P stays in registers. Quad shuffles convert softmax
// layout (cols 2t,2t+1) to PV A-fragment layout (cols t, t+4) — the
// Ss smem buffer, its STS/LDS passes, and one __syncthreads are gone.
// smem = K+V only (25.6 KB) -> 8 CTAs/SM; warps fully independent
// after the single staging sync.
// =====================================================================
constexpr int ATTN_SMEM_B = (80 * DH + 80 * DH) * 4;  // 25,600 B

__global__ void __launch_bounds__(256) attn_kernel(
    const float* __restrict__ q,    // (B*N, 320)
    float* __restrict__ sim,        // (B,H,N,77)
    float* __restrict__ o)          // (B*N, 320)
{
    float* Ks = (float*)smem_raw;              // [80][40]
    float* Vs = Ks + 80 * DH;                  // [80][40]

    const int bh = blockIdx.y;
    const int b = bh >> 3;
    const int h = bh & 7;
    const int tid  = threadIdx.x;
    const int lane = tid & 31;
    const int wid  = tid >> 5;
    const int g = lane >> 2;
    const int t = lane & 3;
    const int nBase = blockIdx.x * 128;
    const int m0 = wid * 16;

    // ---- issue Q fragment loads from global (rows are warp-private) ----
    float qf[5][4];
    {
        const float* qb = q + (size_t)(b * Nn + nBase + m0 + g) * ID + h * DH;
        #pragma unroll
        for (int ks = 0; ks < 5; ks++) {
            const int kc = ks * 8;
            qf[ks][0] = qb[kc + t];
            qf[ks][1] = qb[8 * ID + kc + t];
            qf[ks][2] = qb[kc + t + 4];
            qf[ks][3] = qb[8 * ID + kc + t + 4];
        }
    }

    // ---- stage K, V (tf32, rows 77..79 zeroed) ----
    for (int idx = tid; idx < CN * 10; idx += 256) {
        const int r = idx / 10, c4 = (idx - r * 10) * 4;
        const float* base = g_kv + (size_t)(b * CN + r) * (2 * ID) + h * DH + c4;
        *(uint4*)&Ks[r * DH + c4] = tf32x4(*(const float4*)(base));
        *(uint4*)&Vs[r * DH + c4] = tf32x4(*(const float4*)(base + ID));
    }
    if (tid < 120) {
        Ks[CN * DH + tid] = 0.f;
        Vs[CN * DH + tid] = 0.f;
    }
    __syncthreads();

    // ---- QK^T: warp covers 16 rows x 80 cols ----
    float acc[10][4];
    #pragma unroll
    for (int nt = 0; nt < 10; nt++)
        #pragma unroll
        for (int r = 0; r < 4; r++) acc[nt][r] = 0.f;

    #pragma unroll
    for (int ks = 0; ks < 5; ks++) {
        const int kc = ks * 8;
        const uint32_t a0 = f2tf32(qf[ks][0]);
        const uint32_t a1 = f2tf32(qf[ks][1]);
        const uint32_t a2 = f2tf32(qf[ks][2]);
        const uint32_t a3 = f2tf32(qf[ks][3]);
        #pragma unroll
        for (int nt = 0; nt < 10; nt++) {
            const int n0 = nt * 8 + g;
            uint32_t b0 = __float_as_uint(Ks[n0 * DH + kc + t    ]);
            uint32_t b1 = __float_as_uint(Ks[n0 * DH + kc + t + 4]);
            MMA_TF32(acc[nt], a0, a1, a2, a3, b0, b1);
        }
    }
    // scale
    #pragma unroll
    for (int nt = 0; nt < 10; nt++)
        #pragma unroll
        for (int r = 0; r < 4; r++) acc[nt][r] *= SCALE;

    // ---- sim write straight from registers (scalar stores: stride 77) ----
    {
        float* s0 = sim + ((size_t)bh * Nn + nBase + m0 + g) * CN;
        float* s1 = s0 + 8 * (size_t)CN;
        #pragma unroll
        for (int nt = 0; nt < 10; nt++) {
            const int c = nt * 8 + 2 * t;
            if (c < CN) {
                s0[c] = acc[nt][0];
                s1[c] = acc[nt][2];
            }
            if (c + 1 < CN) {
                s0[c + 1] = acc[nt][1];
                s1[c + 1] = acc[nt][3];
            }
        }
    }

    // ---- softmax in registers ----
    {
        const bool in0 = (t <= 2);   // nt==9 comp0 col = 72+2t < 77
        const bool in1 = (t <= 1);   // nt==9 comp1 col = 73+2t < 77
        float mx0 = -1e30f, mx1 = -1e30f;
        #pragma unroll
        for (int nt = 0; nt < 9; nt++) {
            mx0 = fmaxf(mx0, fmaxf(acc[nt][0], acc[nt][1]));
            mx1 = fmaxf(mx1, fmaxf(acc[nt][2], acc[nt][3]));
        }
        if (in0) { mx0 = fmaxf(mx0, acc[9][0]); mx1 = fmaxf(mx1, acc[9][2]); }
        if (in1) { mx0 = fmaxf(mx0, acc[9][1]); mx1 = fmaxf(mx1, acc[9][3]); }
        mx0 = fmaxf(mx0, __shfl_xor_sync(0xFFFFFFFF, mx0, 1));
        mx0 = fmaxf(mx0, __shfl_xor_sync(0xFFFFFFFF, mx0, 2));
        mx1 = fmaxf(mx1, __shfl_xor_sync(0xFFFFFFFF, mx1, 1));
        mx1 = fmaxf(mx1, __shfl_xor_sync(0xFFFFFFFF, mx1, 2));

        float s0 = 0.f, s1 = 0.f;
        #pragma unroll
        for (int nt = 0; nt < 10; nt++) {
            float e0 = fast_exp(acc[nt][0] - mx0);
            float e1 = fast_exp(acc[nt][1] - mx0);
            float e2 = fast_exp(acc[nt][2] - mx1);
            float e3 = fast_exp(acc[nt][3] - mx1);
            if (nt == 9) {
                if (!in0) { e0 = 0.f; e2 = 0.f; }
                if (!in1) { e1 = 0.f; e3 = 0.f; }
            }
            acc[nt][0] = e0; acc[nt][1] = e1;
            acc[nt][2] = e2; acc[nt][3] = e3;
            s0 += e0 + e1;
            s1 += e2 + e3;
        }
        s0 += __shfl_xor_sync(0xFFFFFFFF, s0, 1);
        s0 += __shfl_xor_sync(0xFFFFFFFF, s0, 2);
        s1 += __shfl_xor_sync(0xFFFFFFFF, s1, 1);
        s1 += __shfl_xor_sync(0xFFFFFFFF, s1, 2);
        const float inv0 = 1.f / s0;
        const float inv1 = 1.f / s1;

        // token-2 reweight: col 2 = nt0, comp0, t==1
        float w = 1.f;
        if (b == 3) w = -2.f; else if (b == 5) w = 5.f;
        if (t == 1) { acc[0][0] *= w; acc[0][2] *= w; }

        // normalize + tf32-round P in registers
        #pragma unroll
        for (int nt = 0; nt < 10; nt++) {
            acc[nt][0] = __uint_as_float(f2tf32(acc[nt][0] * inv0));
            acc[nt][1] = __uint_as_float(f2tf32(acc[nt][1] * inv0));
            acc[nt][2] = __uint_as_float(f2tf32(acc[nt][2] * inv1));
            acc[nt][3] = __uint_as_float(f2tf32(acc[nt][3] * inv1));
        }
    }

    // ---- P V: A-fragments built by quad shuffles from acc ----
    {
        const int base = lane & ~3;
        const int srcA = base | (t >> 1);        // cols kc + t
        const int srcB = base | (2 + (t >> 1));  // cols kc + t + 4
        const bool odd = (t & 1);

        float oacc[5][4];
        #pragma unroll
        for (int nt = 0; nt < 5; nt++)
            #pragma unroll
            for (int r = 0; r < 4; r++) oacc[nt][r] = 0.f;

        #pragma unroll
        for (int ks = 0; ks < 10; ks++) {
            const int kc = ks * 8;
            // fragment a0 = P[row g][kc+t], a1 = P[row g+8][kc+t]
            float xA0 = __shfl_sync(0xFFFFFFFF, acc[ks][0], srcA);
            float yA0 = __shfl_sync(0xFFFFFFFF, acc[ks][1], srcA);
            float xA1 = __shfl_sync(0xFFFFFFFF, acc[ks][2], srcA);
            float yA1 = __shfl_sync(0xFFFFFFFF, acc[ks][3], srcA);
            // fragment a2 = P[row g][kc+t+4], a3 = P[row g+8][kc+t+4]
            float xB0 = __shfl_sync(0xFFFFFFFF, acc[ks][0], srcB);
            float yB0 = __shfl_sync(0xFFFFFFFF, acc[ks][1], srcB);
            float xB1 = __shfl_sync(0xFFFFFFFF, acc[ks][2], srcB);
            float yB1 = __shfl_sync(0xFFFFFFFF, acc[ks][3], srcB);

            uint32_t a0 = __float_as_uint(odd ? yA0 : xA0);
            uint32_t a1 = __float_as_uint(odd ? yA1 : xA1);
            uint32_t a2 = __float_as_uint(odd ? yB0 : xB0);
            uint32_t a3 = __float_as_uint(odd ? yB1 : xB1);

            #pragma unroll
            for (int nt = 0; nt < 5; nt++) {
                const int n0 = nt * 8 + g;
                uint32_t b0 = __float_as_uint(Vs[(kc + t    ) * DH + n0]);
                uint32_t b1 = __float_as_uint(Vs[(kc + t + 4) * DH + n0]);
                MMA_TF32(oacc[nt], a0, a1, a2, a3, b0, b1);
            }
        }

        float* o0 = o + ((size_t)(b * Nn + nBase + m0 + g    )) * ID + h * DH;
        float* o1 = o + ((size_t)(b * Nn + nBase + m0 + g + 8)) * ID + h * DH;
        #pragma unroll
        for (int nt = 0; nt < 5; nt++) {
            const int c = nt * 8 + 2 * t;
            float2 lo, hi;
            lo.x = oacc[nt][0]; lo.y = oacc[nt][1];
            hi.x = oacc[nt][2]; hi.y = oacc[nt][3];
            *(float2*)(o0 + c) = lo;
            *(float2*)(o1 + c) = hi;
        }
    }
}

// =====================================================================
// launch
// =====================================================================
extern "C" void kernel_launch(void* const* d_in, const int* in_sizes, int n_in,
                              void* d_out, int out_size)
{
    const float* x   = (const float*)d_in[0];
    const float* ctx = (const float*)d_in[1];
    const float* Wq  = (const float*)d_in[2];
    const float* Wk  = (const float*)d_in[3];
    const float* Wv  = (const float*)d_in[4];
    const float* Wo  = (const float*)d_in[5];
    const float* bo  = (const float*)d_in[6];
    // d_in[7] = time (unused: reweight always applies for time >= 0)

    float* out = (float*)d_out;                       // (B, N, 320)
    float* sim = out + (size_t)Bn * Nn * QD;          // (B, H, N, 77)

    float *qp = nullptr, *op = nullptr;
    __half* wt = nullptr;
    cudaGetSymbolAddress((void**)&qp, g_q);
    cudaGetSymbolAddress((void**)&op, g_o);
    cudaGetSymbolAddress((void**)&wt, g_wt);

    cudaFuncSetAttribute(attn_kernel, cudaFuncAttributeMaxDynamicSharedMemorySize,
                         ATTN_SMEM_B);

    // transpose + fp16 convert Wq, Wo
    transpose_w<<<dim3(10, 10, 2), dim3(32, 8)>>>(Wq, Wo);

    // K & V projections (one launch)
    sgemm_kv<<<dim3((2 * ID) / 64, (KVROWS + 63) / 64), 256>>>(ctx, Wk, Wv);

    // Q projection (fp16 tensor cores + ldmatrix)
    gemm_h16<false><<<dim3(320 / 64, MROWS / 128), 128>>>(x, wt, nullptr, qp);

    // fused attention (register softmax + shuffle-built PV fragments)
    attn_kernel<<<dim3(Nn / 128, Bn * Hh), 256, ATTN_SMEM_B>>>(qp, sim, op);

    // output projection + bias (fp16 tensor cores + ldmatrix)
    gemm_h16<true><<<dim3(320 / 64, MROWS / 128), 128>>>(op, wt + 320 * 320, bo, out);
}